// round 3
// baseline (speedup 1.0000x reference)
#include <cuda_runtime.h>
#include <math.h>

// ---------------------------------------------------------------------------
// LinearGlobalAttention, N=262144, C=256, fp32 exact.
//   q = elu(x Wq^T)+1 ; k = elu(x Wk^T)+1 ; v = x Wv^T
//   kv = k^T v ; ksum = colsum(k) ; z = 1/max(q ksum, 1e-6)
//   out = z * (q @ (kv Wo^T)) + bo          (M := kv Wo^T precomputed)
// All heavy GEMMs: 128x128 CTA tile, 8x8 micro-tile per thread, K-slices of 16
// through shared memory, inner loop on packed fma.rn.f32x2 (FFMA2).
// ---------------------------------------------------------------------------

#define NN 262144
#define CC 256
#define NT (NN / 128)   // 2048 row tiles

// Scratch (allocation-free rule: __device__ globals)
__device__ float g_q[NN * CC];
__device__ float g_k[NN * CC];
__device__ float g_v[NN * CC];
__device__ float g_kv[CC * CC];
__device__ float g_M[CC * CC];
__device__ float g_ksum[CC];
__device__ float g_z[NN];

// ---------------------------------------------------------------------------
// Shared micro-kernel: 16 K-steps, acc[32] are packed f32x2 pairs holding the
// 8x8 micro-tile (row i, col pair j). A-operand is broadcast-duplicated into a
// packed pair; B-operand pairs come straight from shared memory.
// ---------------------------------------------------------------------------
__device__ __forceinline__ void micro16(const float (*As)[128],
                                        const float (*Bs)[128],
                                        int ty8, int tx8,
                                        unsigned long long* acc)
{
#pragma unroll
    for (int kk = 0; kk < 16; ++kk) {
        float4 a0 = *(const float4*)&As[kk][ty8];
        float4 a1 = *(const float4*)&As[kk][ty8 + 4];
        ulonglong2 b0 = *(const ulonglong2*)&Bs[kk][tx8];
        ulonglong2 b1 = *(const ulonglong2*)&Bs[kk][tx8 + 4];
        unsigned long long bq[4] = {b0.x, b0.y, b1.x, b1.y};
        float av[8] = {a0.x, a0.y, a0.z, a0.w, a1.x, a1.y, a1.z, a1.w};
#pragma unroll
        for (int i = 0; i < 8; ++i) {
            unsigned long long aa;
            asm("mov.b64 %0, {%1, %1};" : "=l"(aa) : "r"(__float_as_uint(av[i])));
#pragma unroll
            for (int j = 0; j < 4; ++j)
                asm("fma.rn.f32x2 %0, %1, %2, %0;"
                    : "+l"(acc[i * 4 + j]) : "l"(aa), "l"(bq[j]));
        }
    }
}

__device__ __forceinline__ float2 unpack2(unsigned long long p)
{
    unsigned int lo, hi;
    asm("mov.b64 {%0, %1}, %2;" : "=r"(lo), "=r"(hi) : "l"(p));
    return make_float2(__uint_as_float(lo), __uint_as_float(hi));
}

// ---------------------------------------------------------------------------
// Zero the accumulation scratch (kv, M, ksum). Must run every launch so the
// graph replays deterministically.
// ---------------------------------------------------------------------------
__global__ void zero_kernel()
{
    int i = blockIdx.x * blockDim.x + threadIdx.x;
    if (i < CC * CC) { g_kv[i] = 0.f; g_M[i] = 0.f; }
    if (i < CC) g_ksum[i] = 0.f;
}

// ---------------------------------------------------------------------------
// Phase 1: q/k/v = act(x W^T). One CTA per 128-row tile; 6 output tiles
// (3 weights x 2 column halves). x and W K-slices streamed via smem (x tile
// stays hot in L2 across the 6 passes).
// ---------------------------------------------------------------------------
__global__ void __launch_bounds__(256, 2)
qkv_kernel(const float* __restrict__ x, const float* __restrict__ Wq,
           const float* __restrict__ Wk, const float* __restrict__ Wv)
{
    __shared__ __align__(16) float As[16][128];   // As[kk][row] = x[r0+row][kc+kk]
    __shared__ __align__(16) float Bs[16][128];   // Bs[kk][col] = W[j0+col][kc+kk]
    const int tid  = threadIdx.x;
    const int r0   = blockIdx.x << 7;
    const int ty8  = (tid >> 4) << 3;
    const int tx8  = (tid & 15) << 3;
    const int lrow = tid >> 1;            // 0..127
    const int lk0  = (tid & 1) << 3;      // 0 or 8

    for (int w = 0; w < 3; ++w) {
        const float* W = (w == 0) ? Wq : (w == 1) ? Wk : Wv;
        float*       O = (w == 0) ? g_q : (w == 1) ? g_k : g_v;
        for (int half = 0; half < 2; ++half) {
            const int j0 = half << 7;
            unsigned long long acc[32];
#pragma unroll
            for (int i = 0; i < 32; ++i) acc[i] = 0ULL;

            for (int kc = 0; kc < CC; kc += 16) {
                const float* xp = x + (size_t)(r0 + lrow) * CC + kc + lk0;
                float4 u0 = *(const float4*)xp;
                float4 u1 = *(const float4*)(xp + 4);
                const float* wp = W + (size_t)(j0 + lrow) * CC + kc + lk0;
                float4 v0 = *(const float4*)wp;
                float4 v1 = *(const float4*)(wp + 4);
                __syncthreads();   // previous micro16 readers done
                As[lk0 + 0][lrow] = u0.x; As[lk0 + 1][lrow] = u0.y;
                As[lk0 + 2][lrow] = u0.z; As[lk0 + 3][lrow] = u0.w;
                As[lk0 + 4][lrow] = u1.x; As[lk0 + 5][lrow] = u1.y;
                As[lk0 + 6][lrow] = u1.z; As[lk0 + 7][lrow] = u1.w;
                Bs[lk0 + 0][lrow] = v0.x; Bs[lk0 + 1][lrow] = v0.y;
                Bs[lk0 + 2][lrow] = v0.z; Bs[lk0 + 3][lrow] = v0.w;
                Bs[lk0 + 4][lrow] = v1.x; Bs[lk0 + 5][lrow] = v1.y;
                Bs[lk0 + 6][lrow] = v1.z; Bs[lk0 + 7][lrow] = v1.w;
                __syncthreads();
                micro16(As, Bs, ty8, tx8, acc);
            }
            __syncthreads();       // protect smem before next tile's writes

            // epilogue: elu(+1) for q,k ; raw for v
#pragma unroll
            for (int i = 0; i < 8; ++i) {
                float vals[8];
#pragma unroll
                for (int j = 0; j < 4; ++j) {
                    float2 f = unpack2(acc[i * 4 + j]);
                    vals[2 * j] = f.x; vals[2 * j + 1] = f.y;
                }
                if (w < 2) {
#pragma unroll
                    for (int j = 0; j < 8; ++j)
                        vals[j] = (vals[j] > 0.f) ? (vals[j] + 1.f) : expf(vals[j]);
                }
                float4* dst = (float4*)(O + (size_t)(r0 + ty8 + i) * CC + j0 + tx8);
                dst[0] = make_float4(vals[0], vals[1], vals[2], vals[3]);
                dst[1] = make_float4(vals[4], vals[5], vals[6], vals[7]);
            }
        }
    }
}

// ---------------------------------------------------------------------------
// ksum[c] = sum_i k[i][c].  512 blocks x 512 rows, coalesced, one atomic per
// (block, column).
// ---------------------------------------------------------------------------
__global__ void __launch_bounds__(256) ksum_kernel()
{
    const int col = threadIdx.x;
    const size_t r0 = (size_t)blockIdx.x * 512;
    float s = 0.f;
    for (int r = 0; r < 512; ++r) s += g_k[(r0 + r) * CC + col];
    atomicAdd(&g_ksum[col], s);
}

// ---------------------------------------------------------------------------
// kv[a][b] = sum_i k[i][a] v[i][b].  Split-K: grid (2,2,128); each CTA reduces
// a 2048-row chunk for one 128x128 output tile, then atomically accumulates.
// ---------------------------------------------------------------------------
__global__ void __launch_bounds__(256, 2) kv_kernel()
{
    __shared__ __align__(16) float As[16][128];   // As[i][a] = k[i0+i][a0+a]
    __shared__ __align__(16) float Bs[16][128];   // Bs[i][b] = v[i0+i][b0+b]
    const int tid = threadIdx.x;
    const int a0  = blockIdx.x << 7;
    const int b0  = blockIdx.y << 7;
    const size_t i0 = (size_t)blockIdx.z * 2048;
    const int ty8 = (tid >> 4) << 3;
    const int tx8 = (tid & 15) << 3;
    const int li  = tid >> 4;             // 0..15
    const int lc  = (tid & 15) << 3;      // 0..120

    unsigned long long acc[32];
#pragma unroll
    for (int i = 0; i < 32; ++i) acc[i] = 0ULL;

    for (int ic = 0; ic < 2048; ic += 16) {
        const float* kp = g_k + (i0 + ic + li) * CC + a0 + lc;
        float4 k0 = *(const float4*)kp;
        float4 k1 = *(const float4*)(kp + 4);
        const float* vp = g_v + (i0 + ic + li) * CC + b0 + lc;
        float4 v0 = *(const float4*)vp;
        float4 v1 = *(const float4*)(vp + 4);
        __syncthreads();
        *(float4*)&As[li][lc]     = k0;  *(float4*)&As[li][lc + 4] = k1;
        *(float4*)&Bs[li][lc]     = v0;  *(float4*)&Bs[li][lc + 4] = v1;
        __syncthreads();
        micro16(As, Bs, ty8, tx8, acc);
    }

#pragma unroll
    for (int i = 0; i < 8; ++i)
#pragma unroll
        for (int j = 0; j < 4; ++j) {
            float2 f = unpack2(acc[i * 4 + j]);
            float* dst = &g_kv[(a0 + ty8 + i) * CC + b0 + tx8 + 2 * j];
            atomicAdd(dst, f.x);
            atomicAdd(dst + 1, f.y);
        }
}

// ---------------------------------------------------------------------------
// M = kv @ Wo^T  (256x256, K=256).  grid (2,2,4): split-K in 64-chunks.
// ---------------------------------------------------------------------------
__global__ void __launch_bounds__(256) m_kernel(const float* __restrict__ Wo)
{
    __shared__ __align__(16) float As[16][128];   // As[kk][a] = kv[a0+a][kb0+kc+kk]
    __shared__ __align__(16) float Bs[16][128];   // Bs[kk][j] = Wo[j0+j][kb0+kc+kk]
    const int tid  = threadIdx.x;
    const int a0   = blockIdx.x << 7;
    const int j0   = blockIdx.y << 7;
    const int kb0  = blockIdx.z << 6;
    const int ty8  = (tid >> 4) << 3;
    const int tx8  = (tid & 15) << 3;
    const int lrow = tid >> 1;
    const int lk0  = (tid & 1) << 3;

    unsigned long long acc[32];
#pragma unroll
    for (int i = 0; i < 32; ++i) acc[i] = 0ULL;

    for (int kc = 0; kc < 64; kc += 16) {
        const float* ap = g_kv + (size_t)(a0 + lrow) * CC + kb0 + kc + lk0;
        float4 u0 = *(const float4*)ap;
        float4 u1 = *(const float4*)(ap + 4);
        const float* wp = Wo + (size_t)(j0 + lrow) * CC + kb0 + kc + lk0;
        float4 v0 = *(const float4*)wp;
        float4 v1 = *(const float4*)(wp + 4);
        __syncthreads();
        As[lk0 + 0][lrow] = u0.x; As[lk0 + 1][lrow] = u0.y;
        As[lk0 + 2][lrow] = u0.z; As[lk0 + 3][lrow] = u0.w;
        As[lk0 + 4][lrow] = u1.x; As[lk0 + 5][lrow] = u1.y;
        As[lk0 + 6][lrow] = u1.z; As[lk0 + 7][lrow] = u1.w;
        Bs[lk0 + 0][lrow] = v0.x; Bs[lk0 + 1][lrow] = v0.y;
        Bs[lk0 + 2][lrow] = v0.z; Bs[lk0 + 3][lrow] = v0.w;
        Bs[lk0 + 4][lrow] = v1.x; Bs[lk0 + 5][lrow] = v1.y;
        Bs[lk0 + 6][lrow] = v1.z; Bs[lk0 + 7][lrow] = v1.w;
        __syncthreads();
        micro16(As, Bs, ty8, tx8, acc);
    }

#pragma unroll
    for (int i = 0; i < 8; ++i)
#pragma unroll
        for (int j = 0; j < 4; ++j) {
            float2 f = unpack2(acc[i * 4 + j]);
            float* dst = &g_M[(a0 + ty8 + i) * CC + j0 + tx8 + 2 * j];
            atomicAdd(dst, f.x);
            atomicAdd(dst + 1, f.y);
        }
}

// ---------------------------------------------------------------------------
// z[i] = 1 / max(dot(q[i,:], ksum), 1e-6).  One warp handles 8 rows.
// ---------------------------------------------------------------------------
__global__ void __launch_bounds__(256) z_kernel()
{
    __shared__ float ks_s[CC];
    const int tid  = threadIdx.x;
    const int wid  = tid >> 5;
    const int lane = tid & 31;
    ks_s[tid] = g_ksum[tid];
    __syncthreads();

    const int base = blockIdx.x * 64 + wid * 8;
    for (int rr = 0; rr < 8; ++rr) {
        const int r = base + rr;
        const float* qp = g_q + (size_t)r * CC;
        float s = 0.f;
#pragma unroll
        for (int c = 0; c < CC; c += 32) s += qp[c + lane] * ks_s[c + lane];
#pragma unroll
        for (int o = 16; o; o >>= 1) s += __shfl_xor_sync(0xFFFFFFFFu, s, o);
        if (lane == 0) g_z[r] = 1.f / fmaxf(s, 1e-6f);
    }
}

// ---------------------------------------------------------------------------
// out = z * (q @ M) + bo.  Same tiling as phase 1; M streamed (L2 resident).
// ---------------------------------------------------------------------------
__global__ void __launch_bounds__(256, 2)
out_kernel(const float* __restrict__ bo, float* __restrict__ out)
{
    __shared__ __align__(16) float As[16][128];   // As[kk][row] = q[r0+row][kc+kk]
    __shared__ __align__(16) float Bs[16][128];   // Bs[kk][j]   = M[kc+kk][j0+j]
    __shared__ float bo_s[CC];
    const int tid  = threadIdx.x;
    const int r0   = blockIdx.x << 7;
    const int ty8  = (tid >> 4) << 3;
    const int tx8  = (tid & 15) << 3;
    const int lrow = tid >> 1;
    const int lk0  = (tid & 1) << 3;
    const int li   = tid >> 4;
    const int lc   = (tid & 15) << 3;

    bo_s[tid] = bo[tid];

    for (int half = 0; half < 2; ++half) {
        const int j0 = half << 7;
        unsigned long long acc[32];
#pragma unroll
        for (int i = 0; i < 32; ++i) acc[i] = 0ULL;

        for (int kc = 0; kc < CC; kc += 16) {
            const float* qp = g_q + (size_t)(r0 + lrow) * CC + kc + lk0;
            float4 u0 = *(const float4*)qp;
            float4 u1 = *(const float4*)(qp + 4);
            const float* mp = g_M + (size_t)(kc + li) * CC + j0 + lc;
            float4 m0 = *(const float4*)mp;
            float4 m1 = *(const float4*)(mp + 4);
            __syncthreads();
            As[lk0 + 0][lrow] = u0.x; As[lk0 + 1][lrow] = u0.y;
            As[lk0 + 2][lrow] = u0.z; As[lk0 + 3][lrow] = u0.w;
            As[lk0 + 4][lrow] = u1.x; As[lk0 + 5][lrow] = u1.y;
            As[lk0 + 6][lrow] = u1.z; As[lk0 + 7][lrow] = u1.w;
            *(float4*)&Bs[li][lc]     = m0;
            *(float4*)&Bs[li][lc + 4] = m1;
            __syncthreads();
            micro16(As, Bs, ty8, tx8, acc);
        }
        __syncthreads();

#pragma unroll
        for (int i = 0; i < 8; ++i) {
            const int row = r0 + ty8 + i;
            const float zr = g_z[row];
            float vals[8];
#pragma unroll
            for (int j = 0; j < 4; ++j) {
                float2 f = unpack2(acc[i * 4 + j]);
                vals[2 * j]     = f.x * zr + bo_s[j0 + tx8 + 2 * j];
                vals[2 * j + 1] = f.y * zr + bo_s[j0 + tx8 + 2 * j + 1];
            }
            float4* dst = (float4*)(out + (size_t)row * CC + j0 + tx8);
            dst[0] = make_float4(vals[0], vals[1], vals[2], vals[3]);
            dst[1] = make_float4(vals[4], vals[5], vals[6], vals[7]);
        }
    }
}

// ---------------------------------------------------------------------------
// Launch: zero -> qkv -> ksum -> kv -> M -> z -> out (default stream ordering).
// ---------------------------------------------------------------------------
extern "C" void kernel_launch(void* const* d_in, const int* in_sizes, int n_in,
                              void* d_out, int out_size)
{
    (void)in_sizes; (void)n_in; (void)out_size;
    const float* x  = (const float*)d_in[0];
    const float* Wq = (const float*)d_in[1];
    const float* Wk = (const float*)d_in[2];
    const float* Wv = (const float*)d_in[3];
    const float* Wo = (const float*)d_in[4];
    const float* bo = (const float*)d_in[5];
    float* out = (float*)d_out;

    zero_kernel<<<256, 256>>>();
    qkv_kernel<<<NT, 256>>>(x, Wq, Wk, Wv);
    ksum_kernel<<<512, 256>>>();
    kv_kernel<<<dim3(2, 2, 128), 256>>>();
    m_kernel<<<dim3(2, 2, 4), 256>>>(Wo);
    z_kernel<<<NN / 64, 256>>>();
    out_kernel<<<NT, 256>>>(bo, out);
}

// round 4
// speedup vs baseline: 1.0004x; 1.0004x over previous
#include <cuda_runtime.h>
#include <math.h>

// ---------------------------------------------------------------------------
// LinearGlobalAttention, N=262144, C=256, fp32 exact.
//   q = elu(x Wq^T)+1 ; k = elu(x Wk^T)+1 ; v = x Wv^T
//   kv = k^T v ; ksum = colsum(k) ; z = 1/max(q ksum, 1e-6)
//   out = z * (q @ (kv Wo^T)) + bo          (M := kv Wo^T precomputed)
// All heavy GEMMs: 128x128 CTA tile, 8x8 micro-tile per thread, K-slices of 16
// through shared memory, inner loop on packed fma.rn.f32x2 (FFMA2).
// ---------------------------------------------------------------------------

#define NN 262144
#define CC 256
#define NT (NN / 128)   // 2048 row tiles

// Scratch (allocation-free rule: __device__ globals)
__device__ float g_q[NN * CC];
__device__ float g_k[NN * CC];
__device__ float g_v[NN * CC];
__device__ float g_kv[CC * CC];
__device__ float g_M[CC * CC];
__device__ float g_ksum[CC];
__device__ float g_z[NN];

// ---------------------------------------------------------------------------
// Shared micro-kernel: 16 K-steps, acc[32] are packed f32x2 pairs holding the
// 8x8 micro-tile (row i, col pair j). A-operand is broadcast-duplicated into a
// packed pair; B-operand pairs come straight from shared memory.
// ---------------------------------------------------------------------------
__device__ __forceinline__ void micro16(const float (*As)[128],
                                        const float (*Bs)[128],
                                        int ty8, int tx8,
                                        unsigned long long* acc)
{
#pragma unroll
    for (int kk = 0; kk < 16; ++kk) {
        float4 a0 = *(const float4*)&As[kk][ty8];
        float4 a1 = *(const float4*)&As[kk][ty8 + 4];
        ulonglong2 b0 = *(const ulonglong2*)&Bs[kk][tx8];
        ulonglong2 b1 = *(const ulonglong2*)&Bs[kk][tx8 + 4];
        unsigned long long bq[4] = {b0.x, b0.y, b1.x, b1.y};
        float av[8] = {a0.x, a0.y, a0.z, a0.w, a1.x, a1.y, a1.z, a1.w};
#pragma unroll
        for (int i = 0; i < 8; ++i) {
            unsigned long long aa;
            asm("mov.b64 %0, {%1, %1};" : "=l"(aa) : "r"(__float_as_uint(av[i])));
#pragma unroll
            for (int j = 0; j < 4; ++j)
                asm("fma.rn.f32x2 %0, %1, %2, %0;"
                    : "+l"(acc[i * 4 + j]) : "l"(aa), "l"(bq[j]));
        }
    }
}

__device__ __forceinline__ float2 unpack2(unsigned long long p)
{
    unsigned int lo, hi;
    asm("mov.b64 {%0, %1}, %2;" : "=r"(lo), "=r"(hi) : "l"(p));
    return make_float2(__uint_as_float(lo), __uint_as_float(hi));
}

// ---------------------------------------------------------------------------
// Zero the accumulation scratch (kv, M, ksum). Must run every launch so the
// graph replays deterministically.
// ---------------------------------------------------------------------------
__global__ void zero_kernel()
{
    int i = blockIdx.x * blockDim.x + threadIdx.x;
    if (i < CC * CC) { g_kv[i] = 0.f; g_M[i] = 0.f; }
    if (i < CC) g_ksum[i] = 0.f;
}

// ---------------------------------------------------------------------------
// Phase 1: q/k/v = act(x W^T). One CTA per 128-row tile; 6 output tiles
// (3 weights x 2 column halves). x and W K-slices streamed via smem (x tile
// stays hot in L2 across the 6 passes).
// ---------------------------------------------------------------------------
__global__ void __launch_bounds__(256, 2)
qkv_kernel(const float* __restrict__ x, const float* __restrict__ Wq,
           const float* __restrict__ Wk, const float* __restrict__ Wv)
{
    __shared__ __align__(16) float As[16][128];   // As[kk][row] = x[r0+row][kc+kk]
    __shared__ __align__(16) float Bs[16][128];   // Bs[kk][col] = W[j0+col][kc+kk]
    const int tid  = threadIdx.x;
    const int r0   = blockIdx.x << 7;
    const int ty8  = (tid >> 4) << 3;
    const int tx8  = (tid & 15) << 3;
    const int lrow = tid >> 1;            // 0..127
    const int lk0  = (tid & 1) << 3;      // 0 or 8

    for (int w = 0; w < 3; ++w) {
        const float* W = (w == 0) ? Wq : (w == 1) ? Wk : Wv;
        float*       O = (w == 0) ? g_q : (w == 1) ? g_k : g_v;
        for (int half = 0; half < 2; ++half) {
            const int j0 = half << 7;
            unsigned long long acc[32];
#pragma unroll
            for (int i = 0; i < 32; ++i) acc[i] = 0ULL;

            for (int kc = 0; kc < CC; kc += 16) {
                const float* xp = x + (size_t)(r0 + lrow) * CC + kc + lk0;
                float4 u0 = *(const float4*)xp;
                float4 u1 = *(const float4*)(xp + 4);
                const float* wp = W + (size_t)(j0 + lrow) * CC + kc + lk0;
                float4 v0 = *(const float4*)wp;
                float4 v1 = *(const float4*)(wp + 4);
                __syncthreads();   // previous micro16 readers done
                As[lk0 + 0][lrow] = u0.x; As[lk0 + 1][lrow] = u0.y;
                As[lk0 + 2][lrow] = u0.z; As[lk0 + 3][lrow] = u0.w;
                As[lk0 + 4][lrow] = u1.x; As[lk0 + 5][lrow] = u1.y;
                As[lk0 + 6][lrow] = u1.z; As[lk0 + 7][lrow] = u1.w;
                Bs[lk0 + 0][lrow] = v0.x; Bs[lk0 + 1][lrow] = v0.y;
                Bs[lk0 + 2][lrow] = v0.z; Bs[lk0 + 3][lrow] = v0.w;
                Bs[lk0 + 4][lrow] = v1.x; Bs[lk0 + 5][lrow] = v1.y;
                Bs[lk0 + 6][lrow] = v1.z; Bs[lk0 + 7][lrow] = v1.w;
                __syncthreads();
                micro16(As, Bs, ty8, tx8, acc);
            }
            __syncthreads();       // protect smem before next tile's writes

            // epilogue: elu(+1) for q,k ; raw for v
#pragma unroll
            for (int i = 0; i < 8; ++i) {
                float vals[8];
#pragma unroll
                for (int j = 0; j < 4; ++j) {
                    float2 f = unpack2(acc[i * 4 + j]);
                    vals[2 * j] = f.x; vals[2 * j + 1] = f.y;
                }
                if (w < 2) {
#pragma unroll
                    for (int j = 0; j < 8; ++j)
                        vals[j] = (vals[j] > 0.f) ? (vals[j] + 1.f) : expf(vals[j]);
                }
                float4* dst = (float4*)(O + (size_t)(r0 + ty8 + i) * CC + j0 + tx8);
                dst[0] = make_float4(vals[0], vals[1], vals[2], vals[3]);
                dst[1] = make_float4(vals[4], vals[5], vals[6], vals[7]);
            }
        }
    }
}

// ---------------------------------------------------------------------------
// ksum[c] = sum_i k[i][c].  512 blocks x 512 rows, coalesced, one atomic per
// (block, column).
// ---------------------------------------------------------------------------
__global__ void __launch_bounds__(256) ksum_kernel()
{
    const int col = threadIdx.x;
    const size_t r0 = (size_t)blockIdx.x * 512;
    float s = 0.f;
    for (int r = 0; r < 512; ++r) s += g_k[(r0 + r) * CC + col];
    atomicAdd(&g_ksum[col], s);
}

// ---------------------------------------------------------------------------
// kv[a][b] = sum_i k[i][a] v[i][b].  Split-K: grid (2,2,128); each CTA reduces
// a 2048-row chunk for one 128x128 output tile, then atomically accumulates.
// ---------------------------------------------------------------------------
__global__ void __launch_bounds__(256, 2) kv_kernel()
{
    __shared__ __align__(16) float As[16][128];   // As[i][a] = k[i0+i][a0+a]
    __shared__ __align__(16) float Bs[16][128];   // Bs[i][b] = v[i0+i][b0+b]
    const int tid = threadIdx.x;
    const int a0  = blockIdx.x << 7;
    const int b0  = blockIdx.y << 7;
    const size_t i0 = (size_t)blockIdx.z * 2048;
    const int ty8 = (tid >> 4) << 3;
    const int tx8 = (tid & 15) << 3;
    const int li  = tid >> 4;             // 0..15
    const int lc  = (tid & 15) << 3;      // 0..120

    unsigned long long acc[32];
#pragma unroll
    for (int i = 0; i < 32; ++i) acc[i] = 0ULL;

    for (int ic = 0; ic < 2048; ic += 16) {
        const float* kp = g_k + (i0 + ic + li) * CC + a0 + lc;
        float4 k0 = *(const float4*)kp;
        float4 k1 = *(const float4*)(kp + 4);
        const float* vp = g_v + (i0 + ic + li) * CC + b0 + lc;
        float4 v0 = *(const float4*)vp;
        float4 v1 = *(const float4*)(vp + 4);
        __syncthreads();
        *(float4*)&As[li][lc]     = k0;  *(float4*)&As[li][lc + 4] = k1;
        *(float4*)&Bs[li][lc]     = v0;  *(float4*)&Bs[li][lc + 4] = v1;
        __syncthreads();
        micro16(As, Bs, ty8, tx8, acc);
    }

#pragma unroll
    for (int i = 0; i < 8; ++i)
#pragma unroll
        for (int j = 0; j < 4; ++j) {
            float2 f = unpack2(acc[i * 4 + j]);
            float* dst = &g_kv[(a0 + ty8 + i) * CC + b0 + tx8 + 2 * j];
            atomicAdd(dst, f.x);
            atomicAdd(dst + 1, f.y);
        }
}

// ---------------------------------------------------------------------------
// M = kv @ Wo^T  (256x256, K=256).  grid (2,2,4): split-K in 64-chunks.
// ---------------------------------------------------------------------------
__global__ void __launch_bounds__(256) m_kernel(const float* __restrict__ Wo)
{
    __shared__ __align__(16) float As[16][128];   // As[kk][a] = kv[a0+a][kb0+kc+kk]
    __shared__ __align__(16) float Bs[16][128];   // Bs[kk][j] = Wo[j0+j][kb0+kc+kk]
    const int tid  = threadIdx.x;
    const int a0   = blockIdx.x << 7;
    const int j0   = blockIdx.y << 7;
    const int kb0  = blockIdx.z << 6;
    const int ty8  = (tid >> 4) << 3;
    const int tx8  = (tid & 15) << 3;
    const int lrow = tid >> 1;
    const int lk0  = (tid & 1) << 3;

    unsigned long long acc[32];
#pragma unroll
    for (int i = 0; i < 32; ++i) acc[i] = 0ULL;

    for (int kc = 0; kc < 64; kc += 16) {
        const float* ap = g_kv + (size_t)(a0 + lrow) * CC + kb0 + kc + lk0;
        float4 u0 = *(const float4*)ap;
        float4 u1 = *(const float4*)(ap + 4);
        const float* wp = Wo + (size_t)(j0 + lrow) * CC + kb0 + kc + lk0;
        float4 v0 = *(const float4*)wp;
        float4 v1 = *(const float4*)(wp + 4);
        __syncthreads();
        As[lk0 + 0][lrow] = u0.x; As[lk0 + 1][lrow] = u0.y;
        As[lk0 + 2][lrow] = u0.z; As[lk0 + 3][lrow] = u0.w;
        As[lk0 + 4][lrow] = u1.x; As[lk0 + 5][lrow] = u1.y;
        As[lk0 + 6][lrow] = u1.z; As[lk0 + 7][lrow] = u1.w;
        Bs[lk0 + 0][lrow] = v0.x; Bs[lk0 + 1][lrow] = v0.y;
        Bs[lk0 + 2][lrow] = v0.z; Bs[lk0 + 3][lrow] = v0.w;
        Bs[lk0 + 4][lrow] = v1.x; Bs[lk0 + 5][lrow] = v1.y;
        Bs[lk0 + 6][lrow] = v1.z; Bs[lk0 + 7][lrow] = v1.w;
        __syncthreads();
        micro16(As, Bs, ty8, tx8, acc);
    }

#pragma unroll
    for (int i = 0; i < 8; ++i)
#pragma unroll
        for (int j = 0; j < 4; ++j) {
            float2 f = unpack2(acc[i * 4 + j]);
            float* dst = &g_M[(a0 + ty8 + i) * CC + j0 + tx8 + 2 * j];
            atomicAdd(dst, f.x);
            atomicAdd(dst + 1, f.y);
        }
}

// ---------------------------------------------------------------------------
// z[i] = 1 / max(dot(q[i,:], ksum), 1e-6).  One warp handles 8 rows.
// ---------------------------------------------------------------------------
__global__ void __launch_bounds__(256) z_kernel()
{
    __shared__ float ks_s[CC];
    const int tid  = threadIdx.x;
    const int wid  = tid >> 5;
    const int lane = tid & 31;
    ks_s[tid] = g_ksum[tid];
    __syncthreads();

    const int base = blockIdx.x * 64 + wid * 8;
    for (int rr = 0; rr < 8; ++rr) {
        const int r = base + rr;
        const float* qp = g_q + (size_t)r * CC;
        float s = 0.f;
#pragma unroll
        for (int c = 0; c < CC; c += 32) s += qp[c + lane] * ks_s[c + lane];
#pragma unroll
        for (int o = 16; o; o >>= 1) s += __shfl_xor_sync(0xFFFFFFFFu, s, o);
        if (lane == 0) g_z[r] = 1.f / fmaxf(s, 1e-6f);
    }
}

// ---------------------------------------------------------------------------
// out = z * (q @ M) + bo.  Same tiling as phase 1; M streamed (L2 resident).
// ---------------------------------------------------------------------------
__global__ void __launch_bounds__(256, 2)
out_kernel(const float* __restrict__ bo, float* __restrict__ out)
{
    __shared__ __align__(16) float As[16][128];   // As[kk][row] = q[r0+row][kc+kk]
    __shared__ __align__(16) float Bs[16][128];   // Bs[kk][j]   = M[kc+kk][j0+j]
    __shared__ float bo_s[CC];
    const int tid  = threadIdx.x;
    const int r0   = blockIdx.x << 7;
    const int ty8  = (tid >> 4) << 3;
    const int tx8  = (tid & 15) << 3;
    const int lrow = tid >> 1;
    const int lk0  = (tid & 1) << 3;
    const int li   = tid >> 4;
    const int lc   = (tid & 15) << 3;

    bo_s[tid] = bo[tid];

    for (int half = 0; half < 2; ++half) {
        const int j0 = half << 7;
        unsigned long long acc[32];
#pragma unroll
        for (int i = 0; i < 32; ++i) acc[i] = 0ULL;

        for (int kc = 0; kc < CC; kc += 16) {
            const float* qp = g_q + (size_t)(r0 + lrow) * CC + kc + lk0;
            float4 u0 = *(const float4*)qp;
            float4 u1 = *(const float4*)(qp + 4);
            const float* mp = g_M + (size_t)(kc + li) * CC + j0 + lc;
            float4 m0 = *(const float4*)mp;
            float4 m1 = *(const float4*)(mp + 4);
            __syncthreads();
            As[lk0 + 0][lrow] = u0.x; As[lk0 + 1][lrow] = u0.y;
            As[lk0 + 2][lrow] = u0.z; As[lk0 + 3][lrow] = u0.w;
            As[lk0 + 4][lrow] = u1.x; As[lk0 + 5][lrow] = u1.y;
            As[lk0 + 6][lrow] = u1.z; As[lk0 + 7][lrow] = u1.w;
            *(float4*)&Bs[li][lc]     = m0;
            *(float4*)&Bs[li][lc + 4] = m1;
            __syncthreads();
            micro16(As, Bs, ty8, tx8, acc);
        }
        __syncthreads();

#pragma unroll
        for (int i = 0; i < 8; ++i) {
            const int row = r0 + ty8 + i;
            const float zr = g_z[row];
            float vals[8];
#pragma unroll
            for (int j = 0; j < 4; ++j) {
                float2 f = unpack2(acc[i * 4 + j]);
                vals[2 * j]     = f.x * zr + bo_s[j0 + tx8 + 2 * j];
                vals[2 * j + 1] = f.y * zr + bo_s[j0 + tx8 + 2 * j + 1];
            }
            float4* dst = (float4*)(out + (size_t)row * CC + j0 + tx8);
            dst[0] = make_float4(vals[0], vals[1], vals[2], vals[3]);
            dst[1] = make_float4(vals[4], vals[5], vals[6], vals[7]);
        }
    }
}

// ---------------------------------------------------------------------------
// Launch: zero -> qkv -> ksum -> kv -> M -> z -> out (default stream ordering).
// ---------------------------------------------------------------------------
extern "C" void kernel_launch(void* const* d_in, const int* in_sizes, int n_in,
                              void* d_out, int out_size)
{
    (void)in_sizes; (void)n_in; (void)out_size;
    const float* x  = (const float*)d_in[0];
    const float* Wq = (const float*)d_in[1];
    const float* Wk = (const float*)d_in[2];
    const float* Wv = (const float*)d_in[3];
    const float* Wo = (const float*)d_in[4];
    const float* bo = (const float*)d_in[5];
    float* out = (float*)d_out;

    zero_kernel<<<256, 256>>>();
    qkv_kernel<<<NT, 256>>>(x, Wq, Wk, Wv);
    ksum_kernel<<<512, 256>>>();
    kv_kernel<<<dim3(2, 2, 128), 256>>>();
    m_kernel<<<dim3(2, 2, 4), 256>>>(Wo);
    z_kernel<<<NN / 64, 256>>>();
    out_kernel<<<NT, 256>>>(bo, out);
}

// round 6
// speedup vs baseline: 1.9012x; 1.9004x over previous
#include <cuda_runtime.h>
#include <cuda_bf16.h>
#include <math.h>

#define NN 262144
#define CC 256

// ---- gmem scratch (__device__ globals per allocation rules) ----
__device__ unsigned g_qpk [(size_t)NN * CC];   // q  packed (hi,lo bf16) [N][C]
__device__ unsigned g_ktpk[(size_t)CC * NN];   // k^T packed [C][N]
__device__ unsigned g_vtpk[(size_t)CC * NN];   // v^T packed [C][N]
__device__ float g_kv[CC * CC];
__device__ float g_Mt[CC * CC];                // Mt[j][c] = (kv Wo^T)[c][j]
__device__ float g_ksum[CC];
__device__ float g_z[NN];

// ---- smem plane layout: 128 rows x 32 bf16, row stride 80 B (16B pad) ----
#define RS  80
#define PAH 0
#define PAL 10240
#define PBH 20480
#define PBL 30720
#define SMB 41984   // 4 planes (40960) + slack; transpose buffer aliases planes

// ------------------------- helpers -------------------------
__device__ __forceinline__ unsigned smem_u32(const void* p){
    unsigned a;
    asm("{ .reg .u64 t; cvta.to.shared.u64 t, %1; cvt.u32.u64 %0, t; }":"=r"(a):"l"(p));
    return a;
}
// packed u32: low16 = bf16(hi), high16 = bf16(residual)
__device__ __forceinline__ unsigned fsplit(float f){
    __nv_bfloat16 h = __float2bfloat16(f);
    __nv_bfloat16 l = __float2bfloat16(f - __bfloat162float(h));
    return (unsigned)__bfloat16_as_ushort(h) | ((unsigned)__bfloat16_as_ushort(l) << 16);
}
__device__ __forceinline__ float pkval(unsigned p){
    return __bfloat162float(__ushort_as_bfloat16((unsigned short)(p & 0xffffu)))
         + __bfloat162float(__ushort_as_bfloat16((unsigned short)(p >> 16)));
}
// 8 packed values -> 16B hi-plane store + 16B lo-plane store
__device__ __forceinline__ void stage8(unsigned char* sm, int plane, int row, int col,
                                       const unsigned* p){
    uint4 h, l;
    h.x=(p[0]&0xffffu)|(p[1]<<16); h.y=(p[2]&0xffffu)|(p[3]<<16);
    h.z=(p[4]&0xffffu)|(p[5]<<16); h.w=(p[6]&0xffffu)|(p[7]<<16);
    l.x=(p[0]>>16)|(p[1]&0xffff0000u); l.y=(p[2]>>16)|(p[3]&0xffff0000u);
    l.z=(p[4]>>16)|(p[5]&0xffff0000u); l.w=(p[6]>>16)|(p[7]&0xffff0000u);
    *(uint4*)(sm + plane +         row*RS + col*2) = h;
    *(uint4*)(sm + plane + 10240 + row*RS + col*2) = l;
}
__device__ __forceinline__ void stage16_f32(unsigned char* sm, int plane, int row, int col,
                                            const float* src){
#pragma unroll
    for (int g = 0; g < 2; ++g){
        float4 a = *(const float4*)(src + g*8);
        float4 b = *(const float4*)(src + g*8 + 4);
        unsigned p[8] = {fsplit(a.x),fsplit(a.y),fsplit(a.z),fsplit(a.w),
                         fsplit(b.x),fsplit(b.y),fsplit(b.z),fsplit(b.w)};
        stage8(sm, plane, row, col + g*8, p);
    }
}
__device__ __forceinline__ void stage16_pk(unsigned char* sm, int plane, int row, int col,
                                           const unsigned* src){
#pragma unroll
    for (int g = 0; g < 2; ++g){
        uint4 A = *(const uint4*)(src + g*8);
        uint4 B = *(const uint4*)(src + g*8 + 4);
        unsigned p[8] = {A.x,A.y,A.z,A.w,B.x,B.y,B.z,B.w};
        stage8(sm, plane, row, col + g*8, p);
    }
}
__device__ __forceinline__ void ldsm4(unsigned* r, unsigned addr){
    asm volatile("ldmatrix.sync.aligned.m8n8.x4.shared.b16 {%0,%1,%2,%3}, [%4];"
        : "=r"(r[0]),"=r"(r[1]),"=r"(r[2]),"=r"(r[3]) : "r"(addr));
}
__device__ __forceinline__ void mma16816(float* c, const unsigned* a, const unsigned* b){
    asm volatile("mma.sync.aligned.m16n8k16.row.col.f32.bf16.bf16.f32 "
        "{%0,%1,%2,%3},{%4,%5,%6,%7},{%8,%9},{%0,%1,%2,%3};"
        : "+f"(c[0]),"+f"(c[1]),"+f"(c[2]),"+f"(c[3])
        : "r"(a[0]),"r"(a[1]),"r"(a[2]),"r"(a[3]), "r"(b[0]),"r"(b[1]));
}
// one K=32 chunk: 2 k16 steps x 3 split terms over warp tile 32x64
__device__ __forceinline__ void chunk_mma(unsigned sb, int wm, int wn, int lane,
                                          float acc[2][8][4]){
    const int arow = wm*32 + (lane & 15);
    const int ak   = (lane >> 4) << 3;
    const int brow = wn*64 + (lane & 7) + ((lane & 16) >> 1);
    const int bk   = lane & 8;
#pragma unroll
    for (int s = 0; s < 2; ++s){
        unsigned ah[2][4], al[2][4], bh[8][2], bl[8][2];
#pragma unroll
        for (int t = 0; t < 2; ++t){
            unsigned base = sb + (unsigned)((arow + 16*t)*RS + (s*16 + ak)*2);
            ldsm4(ah[t], base + PAH);
            ldsm4(al[t], base + PAL);
        }
#pragma unroll
        for (int u = 0; u < 4; ++u){
            unsigned base = sb + (unsigned)((brow + 16*u)*RS + (s*16 + bk)*2);
            unsigned r[4];
            ldsm4(r, base + PBH);
            bh[2*u][0]=r[0]; bh[2*u][1]=r[1]; bh[2*u+1][0]=r[2]; bh[2*u+1][1]=r[3];
            ldsm4(r, base + PBL);
            bl[2*u][0]=r[0]; bl[2*u][1]=r[1]; bl[2*u+1][0]=r[2]; bl[2*u+1][1]=r[3];
        }
#pragma unroll
        for (int t = 0; t < 2; ++t)
#pragma unroll
            for (int u = 0; u < 8; ++u){
                mma16816(acc[t][u], ah[t], bh[u]);
                mma16816(acc[t][u], ah[t], bl[u]);
                mma16816(acc[t][u], al[t], bh[u]);
            }
    }
}
__device__ __forceinline__ float elu1(float f){ return (f > 0.f) ? f + 1.f : expf(f); }

// ------------------------- qkv projections -------------------------
__global__ void __launch_bounds__(256, 2)
qkv_mma(const float* __restrict__ x, const float* __restrict__ Wq,
        const float* __restrict__ Wk, const float* __restrict__ Wv)
{
    __shared__ __align__(128) unsigned char sm[SMB];
    const unsigned sb = smem_u32(sm);
    unsigned* sm32 = (unsigned*)sm;
    const int tid = threadIdx.x, lane = tid & 31, wid = tid >> 5;
    const int wm = wid >> 1, wn = wid & 1;
    const int r0 = blockIdx.x << 7;
    const int srow = tid >> 1, scol = (tid & 1) << 4;

    for (int w = 0; w < 3; ++w){
        const float* W = (w == 0) ? Wq : (w == 1) ? Wk : Wv;
        for (int nh = 0; nh < 2; ++nh){
            float acc[2][8][4];
#pragma unroll
            for (int t = 0; t < 2; ++t)
#pragma unroll
                for (int u = 0; u < 8; ++u)
#pragma unroll
                    for (int e = 0; e < 4; ++e) acc[t][u][e] = 0.f;

            for (int kc = 0; kc < 256; kc += 32){
                __syncthreads();
                stage16_f32(sm, PAH, srow, scol, x + (size_t)(r0 + srow)*CC + kc + scol);
                stage16_f32(sm, PBH, srow, scol, W + (size_t)(nh*128 + srow)*CC + kc + scol);
                __syncthreads();
                chunk_mma(sb, wm, wn, lane, acc);
            }

            if (w == 0){
                // q: elu+1, pack, direct store
#pragma unroll
                for (int t = 0; t < 2; ++t){
                    const int m = wm*32 + 16*t + (lane >> 2);
#pragma unroll
                    for (int u = 0; u < 8; ++u){
                        const int ng = nh*128 + wn*64 + u*8 + 2*(lane & 3);
                        uint2 o;
                        o.x = fsplit(elu1(acc[t][u][0]));
                        o.y = fsplit(elu1(acc[t][u][1]));
                        *(uint2*)(g_qpk + (size_t)(r0 + m)*CC + ng) = o;
                        o.x = fsplit(elu1(acc[t][u][2]));
                        o.y = fsplit(elu1(acc[t][u][3]));
                        *(uint2*)(g_qpk + (size_t)(r0 + m + 8)*CC + ng) = o;
                    }
                }
            } else {
                unsigned* G = (w == 1) ? g_ktpk : g_vtpk;
                for (int h4 = 0; h4 < 2; ++h4){
                    __syncthreads();           // planes / buffer free
                    if (wn == h4){
#pragma unroll
                        for (int t = 0; t < 2; ++t){
                            const int m = wm*32 + 16*t + (lane >> 2);
#pragma unroll
                            for (int u = 0; u < 8; ++u){
                                const int nl = u*8 + 2*(lane & 3);
                                float f0 = acc[t][u][0], f1 = acc[t][u][1];
                                float f2 = acc[t][u][2], f3 = acc[t][u][3];
                                if (w == 1){ f0=elu1(f0); f1=elu1(f1); f2=elu1(f2); f3=elu1(f3); }
                                sm32[(m    )*69 + nl    ] = fsplit(f0);
                                sm32[(m    )*69 + nl + 1] = fsplit(f1);
                                sm32[(m + 8)*69 + nl    ] = fsplit(f2);
                                sm32[(m + 8)*69 + nl + 1] = fsplit(f3);
                            }
                        }
                    }
                    __syncthreads();
                    // flush transposed: 64 n-columns -> gmem rows
#pragma unroll
                    for (int j = 0; j < 8; ++j){
                        const int np = wid + 8*j;
                        const int ng = nh*128 + h4*64 + np;
#pragma unroll
                        for (int i = 0; i < 4; ++i)
                            G[(size_t)ng*NN + r0 + i*32 + lane] = sm32[(i*32 + lane)*69 + np];
                    }
                }
            }
        }
    }
}

// ------------------------- ksum[c] = sum_i k[i][c] -------------------------
__global__ void __launch_bounds__(256) ksum_kernel()
{
    __shared__ float red[256];
    const int c = blockIdx.x, tid = threadIdx.x;
    const unsigned* row = g_ktpk + (size_t)c * NN;
    float s = 0.f;
    for (int i = tid; i < NN; i += 256) s += pkval(row[i]);
    red[tid] = s; __syncthreads();
    for (int o = 128; o; o >>= 1){ if (tid < o) red[tid] += red[tid + o]; __syncthreads(); }
    if (!tid) g_ksum[c] = red[0];
}

// ------------------------- z[i] = 1/max(q[i].ksum, 1e-6) -------------------------
__global__ void __launch_bounds__(256) z_kernel()
{
    __shared__ float ks_s[CC];
    const int tid = threadIdx.x, wid = tid >> 5, lane = tid & 31;
    ks_s[tid] = g_ksum[tid];
    __syncthreads();
    const int base = blockIdx.x*64 + wid*8;
    for (int rr = 0; rr < 8; ++rr){
        const int r = base + rr;
        const unsigned* qp = g_qpk + (size_t)r * CC;
        float s = 0.f;
#pragma unroll
        for (int c = 0; c < CC; c += 32) s += pkval(qp[c + lane]) * ks_s[c + lane];
#pragma unroll
        for (int o = 16; o; o >>= 1) s += __shfl_xor_sync(0xFFFFFFFFu, s, o);
        if (!lane) g_z[r] = 1.f / fmaxf(s, 1e-6f);
    }
}

__global__ void zero_kernel()
{
    int i = blockIdx.x * blockDim.x + threadIdx.x;
    if (i < CC*CC) g_kv[i] = 0.f;
}

// ------------------------- kv = k^T v, split-K -------------------------
__global__ void __launch_bounds__(256, 2) kv_mma()
{
    __shared__ __align__(128) unsigned char sm[SMB];
    const unsigned sb = smem_u32(sm);
    const int tid = threadIdx.x, lane = tid & 31, wid = tid >> 5;
    const int wm = wid >> 1, wn = wid & 1;
    const int a0 = blockIdx.x << 7, b0 = blockIdx.y << 7;
    const size_t i0 = (size_t)blockIdx.z * 4096;
    const int srow = tid >> 1, scol = (tid & 1) << 4;

    float acc[2][8][4];
#pragma unroll
    for (int t = 0; t < 2; ++t)
#pragma unroll
        for (int u = 0; u < 8; ++u)
#pragma unroll
            for (int e = 0; e < 4; ++e) acc[t][u][e] = 0.f;

    for (int ic = 0; ic < 4096; ic += 32){
        __syncthreads();
        stage16_pk(sm, PAH, srow, scol, g_ktpk + (size_t)(a0 + srow)*NN + i0 + ic + scol);
        stage16_pk(sm, PBH, srow, scol, g_vtpk + (size_t)(b0 + srow)*NN + i0 + ic + scol);
        __syncthreads();
        chunk_mma(sb, wm, wn, lane, acc);
    }
#pragma unroll
    for (int t = 0; t < 2; ++t){
        const int m = wm*32 + 16*t + (lane >> 2);
#pragma unroll
        for (int u = 0; u < 8; ++u){
            const int n = wn*64 + u*8 + 2*(lane & 3);
            atomicAdd(&g_kv[(a0 + m    )*CC + b0 + n    ], acc[t][u][0]);
            atomicAdd(&g_kv[(a0 + m    )*CC + b0 + n + 1], acc[t][u][1]);
            atomicAdd(&g_kv[(a0 + m + 8)*CC + b0 + n    ], acc[t][u][2]);
            atomicAdd(&g_kv[(a0 + m + 8)*CC + b0 + n + 1], acc[t][u][3]);
        }
    }
}

// ------------------------- Mt[j][a] = sum_b kv[a][b] Wo[j][b] -------------------------
__global__ void __launch_bounds__(256) m_kernel(const float* __restrict__ Wo)
{
    __shared__ float wo_s[256];
    const int j = blockIdx.x, a = threadIdx.x;
    wo_s[a] = Wo[(size_t)j*CC + a];
    __syncthreads();
    const float* kvr = g_kv + (size_t)a*CC;
    float s = 0.f;
#pragma unroll 8
    for (int b = 0; b < CC; ++b) s += kvr[b] * wo_s[b];
    g_Mt[(size_t)j*CC + a] = s;
}

// ------------------------- out = z * (q @ Mt^T) + bo -------------------------
__global__ void __launch_bounds__(256, 2)
out_mma(const float* __restrict__ bo, float* __restrict__ out)
{
    __shared__ __align__(128) unsigned char sm[SMB];
    __shared__ float bo_s[256];
    const unsigned sb = smem_u32(sm);
    const int tid = threadIdx.x, lane = tid & 31, wid = tid >> 5;
    const int wm = wid >> 1, wn = wid & 1;
    const int r0 = blockIdx.x << 7;
    const int srow = tid >> 1, scol = (tid & 1) << 4;
    bo_s[tid] = bo[tid];

    for (int nh = 0; nh < 2; ++nh){
        float acc[2][8][4];
#pragma unroll
        for (int t = 0; t < 2; ++t)
#pragma unroll
            for (int u = 0; u < 8; ++u)
#pragma unroll
                for (int e = 0; e < 4; ++e) acc[t][u][e] = 0.f;

        for (int kc = 0; kc < 256; kc += 32){
            __syncthreads();
            stage16_pk (sm, PAH, srow, scol, g_qpk + (size_t)(r0 + srow)*CC + kc + scol);
            stage16_f32(sm, PBH, srow, scol, g_Mt  + (size_t)(nh*128 + srow)*CC + kc + scol);
            __syncthreads();
            chunk_mma(sb, wm, wn, lane, acc);
        }
#pragma unroll
        for (int t = 0; t < 2; ++t){
            const int m = wm*32 + 16*t + (lane >> 2);
            const float z0 = g_z[r0 + m], z1 = g_z[r0 + m + 8];
#pragma unroll
            for (int u = 0; u < 8; ++u){
                const int ng = nh*128 + wn*64 + u*8 + 2*(lane & 3);
                float2 o;
                o.x = acc[t][u][0]*z0 + bo_s[ng];
                o.y = acc[t][u][1]*z0 + bo_s[ng + 1];
                *(float2*)(out + (size_t)(r0 + m)*CC + ng) = o;
                o.x = acc[t][u][2]*z1 + bo_s[ng];
                o.y = acc[t][u][3]*z1 + bo_s[ng + 1];
                *(float2*)(out + (size_t)(r0 + m + 8)*CC + ng) = o;
            }
        }
    }
}

// ------------------------- launch -------------------------
extern "C" void kernel_launch(void* const* d_in, const int* in_sizes, int n_in,
                              void* d_out, int out_size)
{
    (void)in_sizes; (void)n_in; (void)out_size;
    const float* x  = (const float*)d_in[0];
    const float* Wq = (const float*)d_in[1];
    const float* Wk = (const float*)d_in[2];
    const float* Wv = (const float*)d_in[3];
    const float* Wo = (const float*)d_in[4];
    const float* bo = (const float*)d_in[5];
    float* out = (float*)d_out;

    zero_kernel<<<256, 256>>>();
    qkv_mma<<<NN/128, 256>>>(x, Wq, Wk, Wv);
    ksum_kernel<<<256, 256>>>();
    kv_mma<<<dim3(2, 2, 64), 256>>>();
    m_kernel<<<256, 256>>>(Wo);
    z_kernel<<<NN/64, 256>>>();
    out_mma<<<NN/128, 256>>>(bo, out);
}

// round 7
// speedup vs baseline: 1.9730x; 1.0378x over previous
#include <cuda_runtime.h>
#include <cuda_bf16.h>
#include <math.h>

#define NN 262144
#define CC 256

// ---- gmem scratch (__device__ globals per allocation rules) ----
__device__ unsigned       g_qpk[(size_t)NN * CC];    // q packed (hi,lo bf16) [N][C]
__device__ unsigned short g_xh [(size_t)NN * CC];    // x split
__device__ unsigned short g_xl [(size_t)NN * CC];
__device__ unsigned short g_wh [3 * CC * CC];        // Wq,Wk,Wv split
__device__ unsigned short g_wl [3 * CC * CC];
__device__ unsigned short g_kth[(size_t)CC * NN];    // k^T split [C][N]
__device__ unsigned short g_ktl[(size_t)CC * NN];
__device__ unsigned short g_vth[(size_t)CC * NN];    // v^T split [C][N]
__device__ unsigned short g_vtl[(size_t)CC * NN];
__device__ unsigned short g_mth[CC * CC];            // Mt split [j][c]
__device__ unsigned short g_mtl[CC * CC];
__device__ float g_kv[CC * CC];
__device__ float g_ksum[CC];

// ---- smem plane layout: 128 rows x 32 bf16, row stride 80 B ----
#define RS  80
#define PAH 0
#define PAL 10240
#define PBH 20480
#define PBL 30720
#define SMB 41984

// ------------------------- helpers -------------------------
__device__ __forceinline__ unsigned smem_u32(const void* p){
    unsigned a;
    asm("{ .reg .u64 t; cvta.to.shared.u64 t, %1; cvt.u32.u64 %0, t; }":"=r"(a):"l"(p));
    return a;
}
__device__ __forceinline__ unsigned fsplit(float f){
    __nv_bfloat16 h = __float2bfloat16(f);
    __nv_bfloat16 l = __float2bfloat16(f - __bfloat162float(h));
    return (unsigned)__bfloat16_as_ushort(h) | ((unsigned)__bfloat16_as_ushort(l) << 16);
}
__device__ __forceinline__ float pkval(unsigned p){
    return __bfloat162float(__ushort_as_bfloat16((unsigned short)(p & 0xffffu)))
         + __bfloat162float(__ushort_as_bfloat16((unsigned short)(p >> 16)));
}
__device__ __forceinline__ void cpa16(unsigned d, const void* s){
    asm volatile("cp.async.cg.shared.global [%0], [%1], 16;" :: "r"(d), "l"(s));
}
__device__ __forceinline__ void cpcommit(){ asm volatile("cp.async.commit_group;" ::: "memory"); }
__device__ __forceinline__ void cpwait(){ asm volatile("cp.async.wait_group 0;" ::: "memory"); }

// 8 packed values -> 16B hi-plane store + 16B lo-plane store (register staging)
__device__ __forceinline__ void stage8(unsigned char* sm, int plane, int row, int col,
                                       const unsigned* p){
    uint4 h, l;
    h.x=(p[0]&0xffffu)|(p[1]<<16); h.y=(p[2]&0xffffu)|(p[3]<<16);
    h.z=(p[4]&0xffffu)|(p[5]<<16); h.w=(p[6]&0xffffu)|(p[7]<<16);
    l.x=(p[0]>>16)|(p[1]&0xffff0000u); l.y=(p[2]>>16)|(p[3]&0xffff0000u);
    l.z=(p[4]>>16)|(p[5]&0xffff0000u); l.w=(p[6]>>16)|(p[7]&0xffff0000u);
    *(uint4*)(sm + plane +         row*RS + col*2) = h;
    *(uint4*)(sm + plane + 10240 + row*RS + col*2) = l;
}
__device__ __forceinline__ void ldsm4(unsigned* r, unsigned addr){
    asm volatile("ldmatrix.sync.aligned.m8n8.x4.shared.b16 {%0,%1,%2,%3}, [%4];"
        : "=r"(r[0]),"=r"(r[1]),"=r"(r[2]),"=r"(r[3]) : "r"(addr));
}
__device__ __forceinline__ void mma16816(float* c, const unsigned* a, const unsigned* b){
    asm volatile("mma.sync.aligned.m16n8k16.row.col.f32.bf16.bf16.f32 "
        "{%0,%1,%2,%3},{%4,%5,%6,%7},{%8,%9},{%0,%1,%2,%3};"
        : "+f"(c[0]),"+f"(c[1]),"+f"(c[2]),"+f"(c[3])
        : "r"(a[0]),"r"(a[1]),"r"(a[2]),"r"(a[3]), "r"(b[0]),"r"(b[1]));
}
// one K=32 chunk: 2 k16 steps x 3 split terms over warp tile 32x64
__device__ __forceinline__ void chunk_mma(unsigned sb, int wm, int wn, int lane,
                                          float acc[2][8][4]){
    const int arow = wm*32 + (lane & 15);
    const int ak   = (lane >> 4) << 3;
    const int brow = wn*64 + (lane & 7) + ((lane & 16) >> 1);
    const int bk   = lane & 8;
#pragma unroll
    for (int s = 0; s < 2; ++s){
        unsigned ah[2][4], al[2][4], bh[8][2], bl[8][2];
#pragma unroll
        for (int t = 0; t < 2; ++t){
            unsigned base = sb + (unsigned)((arow + 16*t)*RS + (s*16 + ak)*2);
            ldsm4(ah[t], base + PAH);
            ldsm4(al[t], base + PAL);
        }
#pragma unroll
        for (int u = 0; u < 4; ++u){
            unsigned base = sb + (unsigned)((brow + 16*u)*RS + (s*16 + bk)*2);
            unsigned r[4];
            ldsm4(r, base + PBH);
            bh[2*u][0]=r[0]; bh[2*u][1]=r[1]; bh[2*u+1][0]=r[2]; bh[2*u+1][1]=r[3];
            ldsm4(r, base + PBL);
            bl[2*u][0]=r[0]; bl[2*u][1]=r[1]; bl[2*u+1][0]=r[2]; bl[2*u+1][1]=r[3];
        }
#pragma unroll
        for (int t = 0; t < 2; ++t)
#pragma unroll
            for (int u = 0; u < 8; ++u){
                mma16816(acc[t][u], ah[t], bh[u]);
                mma16816(acc[t][u], ah[t], bl[u]);
                mma16816(acc[t][u], al[t], bh[u]);
            }
    }
}
__device__ __forceinline__ float elu1(float f){ return (f > 0.f) ? f + 1.f : expf(f); }

// ------------------------- presplit x and W -------------------------
__global__ void __launch_bounds__(256) presplit_x(const float* __restrict__ x)
{
    size_t i = ((size_t)blockIdx.x * 256 + threadIdx.x) * 4;
    float4 v = *(const float4*)(x + i);
    unsigned p0 = fsplit(v.x), p1 = fsplit(v.y), p2 = fsplit(v.z), p3 = fsplit(v.w);
    uint2 h, l;
    h.x = (p0&0xffffu)|(p1<<16); h.y = (p2&0xffffu)|(p3<<16);
    l.x = (p0>>16)|(p1&0xffff0000u); l.y = (p2>>16)|(p3&0xffff0000u);
    *(uint2*)(g_xh + i) = h;
    *(uint2*)(g_xl + i) = l;
}
__global__ void __launch_bounds__(256)
presplit_w(const float* __restrict__ Wq, const float* __restrict__ Wk,
           const float* __restrict__ Wv)
{
    int idx = blockIdx.x * 256 + threadIdx.x;          // 192 blocks
    int w = idx >> 14;
    size_t off = (size_t)w * 65536 + (size_t)(idx & 16383) * 4;
    const float* W = (w == 0) ? Wq : (w == 1) ? Wk : Wv;
    float4 v = *(const float4*)(W + (size_t)(idx & 16383) * 4);
    unsigned p0 = fsplit(v.x), p1 = fsplit(v.y), p2 = fsplit(v.z), p3 = fsplit(v.w);
    uint2 h, l;
    h.x = (p0&0xffffu)|(p1<<16); h.y = (p2&0xffffu)|(p3<<16);
    l.x = (p0>>16)|(p1&0xffff0000u); l.y = (p2>>16)|(p3&0xffff0000u);
    *(uint2*)(g_wh + off) = h;
    *(uint2*)(g_wl + off) = l;
}

__global__ void zero_kernel()
{
    int i = blockIdx.x * blockDim.x + threadIdx.x;
    if (i < CC*CC) g_kv[i] = 0.f;
    if (i < CC) g_ksum[i] = 0.f;
}

// ------------------------- qkv projections (cp.async staging) -------------------------
__global__ void __launch_bounds__(256, 2)
qkv_mma()
{
    __shared__ __align__(128) unsigned char sm[SMB];
    const unsigned sb = smem_u32(sm);
    unsigned* sm32 = (unsigned*)sm;
    const int tid = threadIdx.x, lane = tid & 31, wid = tid >> 5;
    const int wm = wid >> 1, wn = wid & 1;
    const int r0 = blockIdx.x << 7;
    const int row = tid >> 1, e0 = (tid & 1) << 4;
    const unsigned dA = sb + PAH + (unsigned)(row*RS + e0*2);
    const unsigned dB = sb + PBH + (unsigned)(row*RS + e0*2);

    for (int w = 0; w < 3; ++w){
        for (int nh = 0; nh < 2; ++nh){
            float acc[2][8][4];
#pragma unroll
            for (int t = 0; t < 2; ++t)
#pragma unroll
                for (int u = 0; u < 8; ++u)
#pragma unroll
                    for (int e = 0; e < 4; ++e) acc[t][u][e] = 0.f;

            for (int kc = 0; kc < 256; kc += 32){
                __syncthreads();
                const size_t oa = (size_t)(r0 + row)*CC + kc + e0;
                const size_t ob = (size_t)w*65536 + (size_t)(nh*128 + row)*CC + kc + e0;
                cpa16(dA,          g_xh + oa); cpa16(dA + 16,         g_xh + oa + 8);
                cpa16(dA + 10240,  g_xl + oa); cpa16(dA + 10240 + 16, g_xl + oa + 8);
                cpa16(dB,          g_wh + ob); cpa16(dB + 16,         g_wh + ob + 8);
                cpa16(dB + 10240,  g_wl + ob); cpa16(dB + 10240 + 16, g_wl + ob + 8);
                cpcommit(); cpwait();
                __syncthreads();
                chunk_mma(sb, wm, wn, lane, acc);
            }

            if (w == 0){
                // q: elu+1, pack, direct store
#pragma unroll
                for (int t = 0; t < 2; ++t){
                    const int m = wm*32 + 16*t + (lane >> 2);
#pragma unroll
                    for (int u = 0; u < 8; ++u){
                        const int ng = nh*128 + wn*64 + u*8 + 2*(lane & 3);
                        uint2 o;
                        o.x = fsplit(elu1(acc[t][u][0]));
                        o.y = fsplit(elu1(acc[t][u][1]));
                        *(uint2*)(g_qpk + (size_t)(r0 + m)*CC + ng) = o;
                        o.x = fsplit(elu1(acc[t][u][2]));
                        o.y = fsplit(elu1(acc[t][u][3]));
                        *(uint2*)(g_qpk + (size_t)(r0 + m + 8)*CC + ng) = o;
                    }
                }
            } else {
                unsigned short* Gh = (w == 1) ? g_kth : g_vth;
                unsigned short* Gl = (w == 1) ? g_ktl : g_vtl;
                for (int h4 = 0; h4 < 2; ++h4){
                    __syncthreads();
                    if (wn == h4){
#pragma unroll
                        for (int t = 0; t < 2; ++t){
                            const int m = wm*32 + 16*t + (lane >> 2);
#pragma unroll
                            for (int u = 0; u < 8; ++u){
                                const int nl = u*8 + 2*(lane & 3);
                                float f0 = acc[t][u][0], f1 = acc[t][u][1];
                                float f2 = acc[t][u][2], f3 = acc[t][u][3];
                                if (w == 1){ f0=elu1(f0); f1=elu1(f1); f2=elu1(f2); f3=elu1(f3); }
                                sm32[(m    )*69 + nl    ] = fsplit(f0);
                                sm32[(m    )*69 + nl + 1] = fsplit(f1);
                                sm32[(m + 8)*69 + nl    ] = fsplit(f2);
                                sm32[(m + 8)*69 + nl + 1] = fsplit(f3);
                            }
                        }
                    }
                    __syncthreads();
                    // flush transposed + fused ksum (k only)
#pragma unroll
                    for (int j = 0; j < 8; ++j){
                        const int np = wid + 8*j;
                        const int ng = nh*128 + h4*64 + np;
                        float ks = 0.f;
#pragma unroll
                        for (int i = 0; i < 4; ++i){
                            unsigned p = sm32[(i*32 + lane)*69 + np];
                            Gh[(size_t)ng*NN + r0 + i*32 + lane] = (unsigned short)(p & 0xffffu);
                            Gl[(size_t)ng*NN + r0 + i*32 + lane] = (unsigned short)(p >> 16);
                            if (w == 1) ks += pkval(p);
                        }
                        if (w == 1){
#pragma unroll
                            for (int o = 16; o; o >>= 1) ks += __shfl_xor_sync(0xFFFFFFFFu, ks, o);
                            if (!lane) atomicAdd(&g_ksum[ng], ks);
                        }
                    }
                }
            }
        }
    }
}

// ------------------------- kv = k^T v, split-K (cp.async staging) -------------------------
__global__ void __launch_bounds__(256, 2) kv_mma()
{
    __shared__ __align__(128) unsigned char sm[SMB];
    const unsigned sb = smem_u32(sm);
    const int tid = threadIdx.x, lane = tid & 31, wid = tid >> 5;
    const int wm = wid >> 1, wn = wid & 1;
    const int a0 = blockIdx.x << 7, b0 = blockIdx.y << 7;
    const size_t i0 = (size_t)blockIdx.z * 4096;
    const int row = tid >> 1, e0 = (tid & 1) << 4;
    const unsigned dA = sb + PAH + (unsigned)(row*RS + e0*2);
    const unsigned dB = sb + PBH + (unsigned)(row*RS + e0*2);

    float acc[2][8][4];
#pragma unroll
    for (int t = 0; t < 2; ++t)
#pragma unroll
        for (int u = 0; u < 8; ++u)
#pragma unroll
            for (int e = 0; e < 4; ++e) acc[t][u][e] = 0.f;

    for (int ic = 0; ic < 4096; ic += 32){
        __syncthreads();
        const size_t oa = (size_t)(a0 + row)*NN + i0 + ic + e0;
        const size_t ob = (size_t)(b0 + row)*NN + i0 + ic + e0;
        cpa16(dA,          g_kth + oa); cpa16(dA + 16,         g_kth + oa + 8);
        cpa16(dA + 10240,  g_ktl + oa); cpa16(dA + 10240 + 16, g_ktl + oa + 8);
        cpa16(dB,          g_vth + ob); cpa16(dB + 16,         g_vth + ob + 8);
        cpa16(dB + 10240,  g_vtl + ob); cpa16(dB + 10240 + 16, g_vtl + ob + 8);
        cpcommit(); cpwait();
        __syncthreads();
        chunk_mma(sb, wm, wn, lane, acc);
    }
#pragma unroll
    for (int t = 0; t < 2; ++t){
        const int m = wm*32 + 16*t + (lane >> 2);
#pragma unroll
        for (int u = 0; u < 8; ++u){
            const int n = wn*64 + u*8 + 2*(lane & 3);
            atomicAdd(&g_kv[(a0 + m    )*CC + b0 + n    ], acc[t][u][0]);
            atomicAdd(&g_kv[(a0 + m    )*CC + b0 + n + 1], acc[t][u][1]);
            atomicAdd(&g_kv[(a0 + m + 8)*CC + b0 + n    ], acc[t][u][2]);
            atomicAdd(&g_kv[(a0 + m + 8)*CC + b0 + n + 1], acc[t][u][3]);
        }
    }
}

// ------------------------- Mt[j][a] = sum_b kv[a][b] Wo[j][b], split store ---------------
__global__ void __launch_bounds__(256) m_kernel(const float* __restrict__ Wo)
{
    __shared__ float wo_s[256];
    const int j = blockIdx.x, a = threadIdx.x;
    wo_s[a] = Wo[(size_t)j*CC + a];
    __syncthreads();
    const float* kvr = g_kv + (size_t)a*CC;
    float s = 0.f;
#pragma unroll 8
    for (int b = 0; b < CC; ++b) s += kvr[b] * wo_s[b];
    unsigned p = fsplit(s);
    g_mth[j*CC + a] = (unsigned short)(p & 0xffffu);
    g_mtl[j*CC + a] = (unsigned short)(p >> 16);
}

// ------------------------- out = z * (q @ Mt^T) + bo  (z fused) -------------------------
__global__ void __launch_bounds__(256, 2)
out_mma(const float* __restrict__ bo, float* __restrict__ out)
{
    __shared__ __align__(128) unsigned char sm[SMB];
    __shared__ float bo_s[256];
    __shared__ float ks_s[256];
    __shared__ float z_s[128];
    const unsigned sb = smem_u32(sm);
    const int tid = threadIdx.x, lane = tid & 31, wid = tid >> 5;
    const int wm = wid >> 1, wn = wid & 1;
    const int r0 = blockIdx.x << 7;
    const int row = tid >> 1, e0 = (tid & 1) << 4;
    const unsigned dB = sb + PBH + (unsigned)(row*RS + e0*2);
    bo_s[tid] = bo[tid];
    ks_s[tid] = g_ksum[tid];
    __syncthreads();

    float zacc = 0.f;
    for (int nh = 0; nh < 2; ++nh){
        float acc[2][8][4];
#pragma unroll
        for (int t = 0; t < 2; ++t)
#pragma unroll
            for (int u = 0; u < 8; ++u)
#pragma unroll
                for (int e = 0; e < 4; ++e) acc[t][u][e] = 0.f;

        for (int kc = 0; kc < 256; kc += 32){
            __syncthreads();
            // B via cp.async
            const size_t ob = (size_t)(nh*128 + row)*CC + kc + e0;
            cpa16(dB,          g_mth + ob); cpa16(dB + 16,         g_mth + ob + 8);
            cpa16(dB + 10240,  g_mtl + ob); cpa16(dB + 10240 + 16, g_mtl + ob + 8);
            // A via registers (fused z accumulation on nh==0)
            const unsigned* qs = g_qpk + (size_t)(r0 + row)*CC + kc + e0;
#pragma unroll
            for (int g = 0; g < 2; ++g){
                uint4 A = *(const uint4*)(qs + g*8);
                uint4 B = *(const uint4*)(qs + g*8 + 4);
                unsigned p[8] = {A.x,A.y,A.z,A.w,B.x,B.y,B.z,B.w};
                stage8(sm, PAH, row, e0 + g*8, p);
                if (nh == 0){
                    const float* kp = ks_s + kc + e0 + g*8;
#pragma unroll
                    for (int u2 = 0; u2 < 8; ++u2) zacc += pkval(p[u2]) * kp[u2];
                }
            }
            cpcommit(); cpwait();
            __syncthreads();
            chunk_mma(sb, wm, wn, lane, acc);
        }
        if (nh == 0){
            float s = zacc + __shfl_xor_sync(0xFFFFFFFFu, zacc, 1);
            if (!(tid & 1)) z_s[row] = 1.f / fmaxf(s, 1e-6f);
        }
        __syncthreads();

#pragma unroll
        for (int t = 0; t < 2; ++t){
            const int m = wm*32 + 16*t + (lane >> 2);
            const float z0 = z_s[m], z1 = z_s[m + 8];
#pragma unroll
            for (int u = 0; u < 8; ++u){
                const int ng = nh*128 + wn*64 + u*8 + 2*(lane & 3);
                float2 o;
                o.x = acc[t][u][0]*z0 + bo_s[ng];
                o.y = acc[t][u][1]*z0 + bo_s[ng + 1];
                *(float2*)(out + (size_t)(r0 + m)*CC + ng) = o;
                o.x = acc[t][u][2]*z1 + bo_s[ng];
                o.y = acc[t][u][3]*z1 + bo_s[ng + 1];
                *(float2*)(out + (size_t)(r0 + m + 8)*CC + ng) = o;
            }
        }
    }
}

// ------------------------- launch -------------------------
extern "C" void kernel_launch(void* const* d_in, const int* in_sizes, int n_in,
                              void* d_out, int out_size)
{
    (void)in_sizes; (void)n_in; (void)out_size;
    const float* x  = (const float*)d_in[0];
    const float* Wq = (const float*)d_in[1];
    const float* Wk = (const float*)d_in[2];
    const float* Wv = (const float*)d_in[3];
    const float* Wo = (const float*)d_in[4];
    const float* bo = (const float*)d_in[5];
    float* out = (float*)d_out;

    zero_kernel<<<256, 256>>>();
    presplit_x<<<65536, 256>>>(x);
    presplit_w<<<192, 256>>>(Wq, Wk, Wv);
    qkv_mma<<<NN/128, 256>>>();
    kv_mma<<<dim3(2, 2, 64), 256>>>();
    m_kernel<<<256, 256>>>(Wo);
    out_mma<<<NN/128, 256>>>(bo, out);
}

// round 8
// speedup vs baseline: 1.9774x; 1.0022x over previous
#include <cuda_runtime.h>
#include <cuda_bf16.h>
#include <math.h>

#define NN 262144
#define CC 256

// ---- gmem scratch (__device__ globals per allocation rules) ----
__device__ unsigned       g_qpk[(size_t)NN * CC];    // q packed (hi,lo bf16) [N][C]
__device__ unsigned short g_xh [(size_t)NN * CC];    // x split
__device__ unsigned short g_xl [(size_t)NN * CC];
__device__ unsigned short g_wh [3 * CC * CC];        // Wq,Wk,Wv split
__device__ unsigned short g_wl [3 * CC * CC];
__device__ unsigned short g_kth[(size_t)CC * NN];    // k^T split [C][N]
__device__ unsigned short g_ktl[(size_t)CC * NN];
__device__ unsigned short g_vth[(size_t)CC * NN];    // v^T split [C][N]
__device__ unsigned short g_vtl[(size_t)CC * NN];
__device__ unsigned short g_mth[CC * CC];            // Mt split [j][c]
__device__ unsigned short g_mtl[CC * CC];
__device__ float g_kv[CC * CC];
__device__ float g_ksum[CC];

// ---- smem: two stages of 4 planes (128 rows x 32 bf16, row stride 80B) ----
#define RS   80
#define PAH  0
#define PAL  10240
#define PBH  20480
#define PBL  30720
#define SS   40960            // bytes per stage
#define SMEM_DYN (2*SS + 3072)   // + bo/ks/z tail for out_mma

// ------------------------- helpers -------------------------
__device__ __forceinline__ unsigned smem_u32(const void* p){
    unsigned a;
    asm("{ .reg .u64 t; cvta.to.shared.u64 t, %1; cvt.u32.u64 %0, t; }":"=r"(a):"l"(p));
    return a;
}
__device__ __forceinline__ unsigned fsplit(float f){
    __nv_bfloat16 h = __float2bfloat16(f);
    __nv_bfloat16 l = __float2bfloat16(f - __bfloat162float(h));
    return (unsigned)__bfloat16_as_ushort(h) | ((unsigned)__bfloat16_as_ushort(l) << 16);
}
__device__ __forceinline__ float pkval(unsigned p){
    return __bfloat162float(__ushort_as_bfloat16((unsigned short)(p & 0xffffu)))
         + __bfloat162float(__ushort_as_bfloat16((unsigned short)(p >> 16)));
}
__device__ __forceinline__ void cpa16(unsigned d, const void* s){
    asm volatile("cp.async.cg.shared.global [%0], [%1], 16;" :: "r"(d), "l"(s));
}
__device__ __forceinline__ void cpcommit(){ asm volatile("cp.async.commit_group;" ::: "memory"); }
template<int N>
__device__ __forceinline__ void cpwaitg(){ asm volatile("cp.async.wait_group %0;" :: "n"(N) : "memory"); }

// 8 packed values -> 16B hi-plane + 16B lo-plane stores (register staging)
__device__ __forceinline__ void stage8(unsigned char* smb, int row, int col,
                                       const unsigned* p){
    uint4 h, l;
    h.x=(p[0]&0xffffu)|(p[1]<<16); h.y=(p[2]&0xffffu)|(p[3]<<16);
    h.z=(p[4]&0xffffu)|(p[5]<<16); h.w=(p[6]&0xffffu)|(p[7]<<16);
    l.x=(p[0]>>16)|(p[1]&0xffff0000u); l.y=(p[2]>>16)|(p[3]&0xffff0000u);
    l.z=(p[4]>>16)|(p[5]&0xffff0000u); l.w=(p[6]>>16)|(p[7]&0xffff0000u);
    *(uint4*)(smb + PAH + row*RS + col*2) = h;
    *(uint4*)(smb + PAL + row*RS + col*2) = l;
}
__device__ __forceinline__ void ldsm4(unsigned* r, unsigned addr){
    asm volatile("ldmatrix.sync.aligned.m8n8.x4.shared.b16 {%0,%1,%2,%3}, [%4];"
        : "=r"(r[0]),"=r"(r[1]),"=r"(r[2]),"=r"(r[3]) : "r"(addr));
}
__device__ __forceinline__ void mma16816(float* c, const unsigned* a, const unsigned* b){
    asm volatile("mma.sync.aligned.m16n8k16.row.col.f32.bf16.bf16.f32 "
        "{%0,%1,%2,%3},{%4,%5,%6,%7},{%8,%9},{%0,%1,%2,%3};"
        : "+f"(c[0]),"+f"(c[1]),"+f"(c[2]),"+f"(c[3])
        : "r"(a[0]),"r"(a[1]),"r"(a[2]),"r"(a[3]), "r"(b[0]),"r"(b[1]));
}
// one K=32 chunk: 2 k16 steps x 3 split terms over warp tile 32x64
__device__ __forceinline__ void chunk_mma(unsigned sbase, int wm, int wn, int lane,
                                          float acc[2][8][4]){
    const int arow = wm*32 + (lane & 15);
    const int ak   = (lane >> 4) << 3;
    const int brow = wn*64 + (lane & 7) + ((lane & 16) >> 1);
    const int bk   = lane & 8;
#pragma unroll
    for (int s = 0; s < 2; ++s){
        unsigned ah[2][4], al[2][4], bh[8][2], bl[8][2];
#pragma unroll
        for (int t = 0; t < 2; ++t){
            unsigned base = sbase + (unsigned)((arow + 16*t)*RS + (s*16 + ak)*2);
            ldsm4(ah[t], base + PAH);
            ldsm4(al[t], base + PAL);
        }
#pragma unroll
        for (int u = 0; u < 4; ++u){
            unsigned base = sbase + (unsigned)((brow + 16*u)*RS + (s*16 + bk)*2);
            unsigned r[4];
            ldsm4(r, base + PBH);
            bh[2*u][0]=r[0]; bh[2*u][1]=r[1]; bh[2*u+1][0]=r[2]; bh[2*u+1][1]=r[3];
            ldsm4(r, base + PBL);
            bl[2*u][0]=r[0]; bl[2*u][1]=r[1]; bl[2*u+1][0]=r[2]; bl[2*u+1][1]=r[3];
        }
#pragma unroll
        for (int t = 0; t < 2; ++t)
#pragma unroll
            for (int u = 0; u < 8; ++u){
                mma16816(acc[t][u], ah[t], bh[u]);
                mma16816(acc[t][u], ah[t], bl[u]);
                mma16816(acc[t][u], al[t], bh[u]);
            }
    }
}
__device__ __forceinline__ float elu1(float f){ return (f > 0.f) ? f + 1.f : expf(f); }

// ------------------------- presplit x and W -------------------------
__global__ void __launch_bounds__(256) presplit_x(const float* __restrict__ x)
{
    size_t i = ((size_t)blockIdx.x * 256 + threadIdx.x) * 4;
    float4 v = *(const float4*)(x + i);
    unsigned p0 = fsplit(v.x), p1 = fsplit(v.y), p2 = fsplit(v.z), p3 = fsplit(v.w);
    uint2 h, l;
    h.x = (p0&0xffffu)|(p1<<16); h.y = (p2&0xffffu)|(p3<<16);
    l.x = (p0>>16)|(p1&0xffff0000u); l.y = (p2>>16)|(p3&0xffff0000u);
    *(uint2*)(g_xh + i) = h;
    *(uint2*)(g_xl + i) = l;
}
__global__ void __launch_bounds__(256)
presplit_w(const float* __restrict__ Wq, const float* __restrict__ Wk,
           const float* __restrict__ Wv)
{
    int idx = blockIdx.x * 256 + threadIdx.x;
    int w = idx >> 14;
    size_t off = (size_t)w * 65536 + (size_t)(idx & 16383) * 4;
    const float* W = (w == 0) ? Wq : (w == 1) ? Wk : Wv;
    float4 v = *(const float4*)(W + (size_t)(idx & 16383) * 4);
    unsigned p0 = fsplit(v.x), p1 = fsplit(v.y), p2 = fsplit(v.z), p3 = fsplit(v.w);
    uint2 h, l;
    h.x = (p0&0xffffu)|(p1<<16); h.y = (p2&0xffffu)|(p3<<16);
    l.x = (p0>>16)|(p1&0xffff0000u); l.y = (p2>>16)|(p3&0xffff0000u);
    *(uint2*)(g_wh + off) = h;
    *(uint2*)(g_wl + off) = l;
}

__global__ void zero_kernel()
{
    int i = blockIdx.x * blockDim.x + threadIdx.x;
    if (i < CC*CC) g_kv[i] = 0.f;
    if (i < CC) g_ksum[i] = 0.f;
}

// ------------------------- qkv projections (2-stage pipeline) -------------------------
__global__ void __launch_bounds__(256, 2)
qkv_mma()
{
    extern __shared__ __align__(128) unsigned char sm[];
    const unsigned sb = smem_u32(sm);
    unsigned* sm32 = (unsigned*)sm;
    const int tid = threadIdx.x, lane = tid & 31, wid = tid >> 5;
    const int wm = wid >> 1, wn = wid & 1;
    const int r0 = blockIdx.x << 7;
    const int row = tid >> 1, e0 = (tid & 1) << 4;
    const unsigned dOff = (unsigned)(row*RS + e0*2);

    for (int w = 0; w < 3; ++w){
        for (int nh = 0; nh < 2; ++nh){
            float acc[2][8][4];
#pragma unroll
            for (int t = 0; t < 2; ++t)
#pragma unroll
                for (int u = 0; u < 8; ++u)
#pragma unroll
                    for (int e = 0; e < 4; ++e) acc[t][u][e] = 0.f;

            auto issue = [&](int c, int buf){
                const size_t oa = (size_t)(r0 + row)*CC + c*32 + e0;
                const size_t ob = (size_t)w*65536 + (size_t)(nh*128 + row)*CC + c*32 + e0;
                const unsigned d = sb + (unsigned)(buf*SS) + dOff;
                cpa16(d + PAH, g_xh + oa); cpa16(d + PAH + 16, g_xh + oa + 8);
                cpa16(d + PAL, g_xl + oa); cpa16(d + PAL + 16, g_xl + oa + 8);
                cpa16(d + PBH, g_wh + ob); cpa16(d + PBH + 16, g_wh + ob + 8);
                cpa16(d + PBL, g_wl + ob); cpa16(d + PBL + 16, g_wl + ob + 8);
                cpcommit();
            };
            issue(0, 0);
            for (int c = 0; c < 8; ++c){
                if (c < 7){ issue(c + 1, (c + 1) & 1); cpwaitg<1>(); }
                else cpwaitg<0>();
                __syncthreads();
                chunk_mma(sb + (unsigned)((c & 1)*SS), wm, wn, lane, acc);
                __syncthreads();
            }

            if (w == 0){
#pragma unroll
                for (int t = 0; t < 2; ++t){
                    const int m = wm*32 + 16*t + (lane >> 2);
#pragma unroll
                    for (int u = 0; u < 8; ++u){
                        const int ng = nh*128 + wn*64 + u*8 + 2*(lane & 3);
                        uint2 o;
                        o.x = fsplit(elu1(acc[t][u][0]));
                        o.y = fsplit(elu1(acc[t][u][1]));
                        *(uint2*)(g_qpk + (size_t)(r0 + m)*CC + ng) = o;
                        o.x = fsplit(elu1(acc[t][u][2]));
                        o.y = fsplit(elu1(acc[t][u][3]));
                        *(uint2*)(g_qpk + (size_t)(r0 + m + 8)*CC + ng) = o;
                    }
                }
            } else {
                unsigned short* Gh = (w == 1) ? g_kth : g_vth;
                unsigned short* Gl = (w == 1) ? g_ktl : g_vtl;
                for (int h4 = 0; h4 < 2; ++h4){
                    __syncthreads();
                    if (wn == h4){
#pragma unroll
                        for (int t = 0; t < 2; ++t){
                            const int m = wm*32 + 16*t + (lane >> 2);
#pragma unroll
                            for (int u = 0; u < 8; ++u){
                                const int nl = u*8 + 2*(lane & 3);
                                float f0 = acc[t][u][0], f1 = acc[t][u][1];
                                float f2 = acc[t][u][2], f3 = acc[t][u][3];
                                if (w == 1){ f0=elu1(f0); f1=elu1(f1); f2=elu1(f2); f3=elu1(f3); }
                                sm32[(m    )*69 + nl    ] = fsplit(f0);
                                sm32[(m    )*69 + nl + 1] = fsplit(f1);
                                sm32[(m + 8)*69 + nl    ] = fsplit(f2);
                                sm32[(m + 8)*69 + nl + 1] = fsplit(f3);
                            }
                        }
                    }
                    __syncthreads();
#pragma unroll
                    for (int j = 0; j < 8; ++j){
                        const int np = wid + 8*j;
                        const int ng = nh*128 + h4*64 + np;
                        float ks = 0.f;
#pragma unroll
                        for (int i = 0; i < 4; ++i){
                            unsigned p = sm32[(i*32 + lane)*69 + np];
                            Gh[(size_t)ng*NN + r0 + i*32 + lane] = (unsigned short)(p & 0xffffu);
                            Gl[(size_t)ng*NN + r0 + i*32 + lane] = (unsigned short)(p >> 16);
                            if (w == 1) ks += pkval(p);
                        }
                        if (w == 1){
#pragma unroll
                            for (int o = 16; o; o >>= 1) ks += __shfl_xor_sync(0xFFFFFFFFu, ks, o);
                            if (!lane) atomicAdd(&g_ksum[ng], ks);
                        }
                    }
                }
                __syncthreads();   // sm32 readers done before next pass prefetches buf0
            }
        }
    }
}

// ------------------------- kv = k^T v, split-K (2-stage pipeline) -------------------------
__global__ void __launch_bounds__(256, 2) kv_mma()
{
    extern __shared__ __align__(128) unsigned char sm[];
    const unsigned sb = smem_u32(sm);
    const int tid = threadIdx.x, lane = tid & 31, wid = tid >> 5;
    const int wm = wid >> 1, wn = wid & 1;
    const int a0 = blockIdx.x << 7, b0 = blockIdx.y << 7;
    const size_t i0 = (size_t)blockIdx.z * 4096;
    const int row = tid >> 1, e0 = (tid & 1) << 4;
    const unsigned dOff = (unsigned)(row*RS + e0*2);

    float acc[2][8][4];
#pragma unroll
    for (int t = 0; t < 2; ++t)
#pragma unroll
        for (int u = 0; u < 8; ++u)
#pragma unroll
            for (int e = 0; e < 4; ++e) acc[t][u][e] = 0.f;

    auto issue = [&](int c, int buf){
        const size_t oa = (size_t)(a0 + row)*NN + i0 + c*32 + e0;
        const size_t ob = (size_t)(b0 + row)*NN + i0 + c*32 + e0;
        const unsigned d = sb + (unsigned)(buf*SS) + dOff;
        cpa16(d + PAH, g_kth + oa); cpa16(d + PAH + 16, g_kth + oa + 8);
        cpa16(d + PAL, g_ktl + oa); cpa16(d + PAL + 16, g_ktl + oa + 8);
        cpa16(d + PBH, g_vth + ob); cpa16(d + PBH + 16, g_vth + ob + 8);
        cpa16(d + PBL, g_vtl + ob); cpa16(d + PBL + 16, g_vtl + ob + 8);
        cpcommit();
    };
    issue(0, 0);
    for (int c = 0; c < 128; ++c){
        if (c < 127){ issue(c + 1, (c + 1) & 1); cpwaitg<1>(); }
        else cpwaitg<0>();
        __syncthreads();
        chunk_mma(sb + (unsigned)((c & 1)*SS), wm, wn, lane, acc);
        __syncthreads();
    }
#pragma unroll
    for (int t = 0; t < 2; ++t){
        const int m = wm*32 + 16*t + (lane >> 2);
#pragma unroll
        for (int u = 0; u < 8; ++u){
            const int n = wn*64 + u*8 + 2*(lane & 3);
            atomicAdd(&g_kv[(a0 + m    )*CC + b0 + n    ], acc[t][u][0]);
            atomicAdd(&g_kv[(a0 + m    )*CC + b0 + n + 1], acc[t][u][1]);
            atomicAdd(&g_kv[(a0 + m + 8)*CC + b0 + n    ], acc[t][u][2]);
            atomicAdd(&g_kv[(a0 + m + 8)*CC + b0 + n + 1], acc[t][u][3]);
        }
    }
}

// ------------------------- Mt[j][a] = sum_b kv[a][b] Wo[j][b], split store ---------------
__global__ void __launch_bounds__(256) m_kernel(const float* __restrict__ Wo)
{
    __shared__ float wo_s[256];
    const int j = blockIdx.x, a = threadIdx.x;
    wo_s[a] = Wo[(size_t)j*CC + a];
    __syncthreads();
    const float* kvr = g_kv + (size_t)a*CC;
    float s = 0.f;
#pragma unroll 8
    for (int b = 0; b < CC; ++b) s += kvr[b] * wo_s[b];
    unsigned p = fsplit(s);
    g_mth[j*CC + a] = (unsigned short)(p & 0xffffu);
    g_mtl[j*CC + a] = (unsigned short)(p >> 16);
}

// ------------------------- out = z * (q @ Mt^T) + bo  (z fused, B pipelined) -------------
__global__ void __launch_bounds__(256, 2)
out_mma(const float* __restrict__ bo, float* __restrict__ out)
{
    extern __shared__ __align__(128) unsigned char sm[];
    const unsigned sb = smem_u32(sm);
    float* bo_s = (float*)(sm + 2*SS);
    float* ks_s = bo_s + 256;
    float* z_s  = ks_s + 256;
    const int tid = threadIdx.x, lane = tid & 31, wid = tid >> 5;
    const int wm = wid >> 1, wn = wid & 1;
    const int r0 = blockIdx.x << 7;
    const int row = tid >> 1, e0 = (tid & 1) << 4;
    const unsigned dOff = (unsigned)(row*RS + e0*2);
    bo_s[tid] = bo[tid];
    ks_s[tid] = g_ksum[tid];
    __syncthreads();

    float zacc = 0.f;
    for (int nh = 0; nh < 2; ++nh){
        float acc[2][8][4];
#pragma unroll
        for (int t = 0; t < 2; ++t)
#pragma unroll
            for (int u = 0; u < 8; ++u)
#pragma unroll
                for (int e = 0; e < 4; ++e) acc[t][u][e] = 0.f;

        auto issueB = [&](int c, int buf){
            const size_t ob = (size_t)(nh*128 + row)*CC + c*32 + e0;
            const unsigned d = sb + (unsigned)(buf*SS) + dOff;
            cpa16(d + PBH, g_mth + ob); cpa16(d + PBH + 16, g_mth + ob + 8);
            cpa16(d + PBL, g_mtl + ob); cpa16(d + PBL + 16, g_mtl + ob + 8);
            cpcommit();
        };
        issueB(0, 0);
        for (int c = 0; c < 8; ++c){
            if (c < 7) issueB(c + 1, (c + 1) & 1);
            // A register staging into the live buffer (+ fused z on nh==0)
            {
                unsigned char* smb = sm + (c & 1)*SS;
                const unsigned* qs = g_qpk + (size_t)(r0 + row)*CC + c*32 + e0;
#pragma unroll
                for (int g = 0; g < 2; ++g){
                    uint4 A = *(const uint4*)(qs + g*8);
                    uint4 B = *(const uint4*)(qs + g*8 + 4);
                    unsigned p[8] = {A.x,A.y,A.z,A.w,B.x,B.y,B.z,B.w};
                    stage8(smb, row, e0 + g*8, p);
                    if (nh == 0){
                        const float* kp = ks_s + c*32 + e0 + g*8;
#pragma unroll
                        for (int u2 = 0; u2 < 8; ++u2) zacc += pkval(p[u2]) * kp[u2];
                    }
                }
            }
            if (c < 7) cpwaitg<1>(); else cpwaitg<0>();
            __syncthreads();
            chunk_mma(sb + (unsigned)((c & 1)*SS), wm, wn, lane, acc);
            __syncthreads();
        }
        if (nh == 0){
            float s = zacc + __shfl_xor_sync(0xFFFFFFFFu, zacc, 1);
            if (!(tid & 1)) z_s[row] = 1.f / fmaxf(s, 1e-6f);
        }
        __syncthreads();

#pragma unroll
        for (int t = 0; t < 2; ++t){
            const int m = wm*32 + 16*t + (lane >> 2);
            const float z0 = z_s[m], z1 = z_s[m + 8];
#pragma unroll
            for (int u = 0; u < 8; ++u){
                const int ng = nh*128 + wn*64 + u*8 + 2*(lane & 3);
                float2 o;
                o.x = acc[t][u][0]*z0 + bo_s[ng];
                o.y = acc[t][u][1]*z0 + bo_s[ng + 1];
                *(float2*)(out + (size_t)(r0 + m)*CC + ng) = o;
                o.x = acc[t][u][2]*z1 + bo_s[ng];
                o.y = acc[t][u][3]*z1 + bo_s[ng + 1];
                *(float2*)(out + (size_t)(r0 + m + 8)*CC + ng) = o;
            }
        }
    }
}

// ------------------------- launch -------------------------
extern "C" void kernel_launch(void* const* d_in, const int* in_sizes, int n_in,
                              void* d_out, int out_size)
{
    (void)in_sizes; (void)n_in; (void)out_size;
    const float* x  = (const float*)d_in[0];
    const float* Wq = (const float*)d_in[1];
    const float* Wk = (const float*)d_in[2];
    const float* Wv = (const float*)d_in[3];
    const float* Wo = (const float*)d_in[4];
    const float* bo = (const float*)d_in[5];
    float* out = (float*)d_out;

    static int inited = 0;
    if (!inited){
        cudaFuncSetAttribute(qkv_mma, cudaFuncAttributeMaxDynamicSharedMemorySize, SMEM_DYN);
        cudaFuncSetAttribute(kv_mma,  cudaFuncAttributeMaxDynamicSharedMemorySize, SMEM_DYN);
        cudaFuncSetAttribute(out_mma, cudaFuncAttributeMaxDynamicSharedMemorySize, SMEM_DYN);
        inited = 1;
    }

    zero_kernel<<<256, 256>>>();
    presplit_x<<<65536, 256>>>(x);
    presplit_w<<<192, 256>>>(Wq, Wk, Wv);
    qkv_mma<<<NN/128, 256, SMEM_DYN>>>();
    kv_mma<<<dim3(2, 2, 64), 256, SMEM_DYN>>>();
    m_kernel<<<256, 256>>>(Wo);
    out_mma<<<NN/128, 256, SMEM_DYN>>>(bo, out);
}

// round 9
// speedup vs baseline: 2.2718x; 1.1489x over previous
#include <cuda_runtime.h>
#include <cuda_bf16.h>
#include <math.h>

#define NN 262144
#define CC 256

// ---- gmem scratch (__device__ globals per allocation rules) ----
__device__ unsigned       g_qpk[(size_t)NN * CC];    // q packed (hi,lo bf16) [N][C]
__device__ unsigned short g_xh [(size_t)NN * CC];    // x split
__device__ unsigned short g_xl [(size_t)NN * CC];
__device__ unsigned short g_wh [3 * CC * CC];        // Wq,Wk,Wv split
__device__ unsigned short g_wl [3 * CC * CC];
__device__ unsigned short g_kth[(size_t)CC * NN];    // k^T split [C][N]
__device__ unsigned short g_ktl[(size_t)CC * NN];
__device__ unsigned short g_vth[(size_t)CC * NN];    // v^T split [C][N]
__device__ unsigned short g_vtl[(size_t)CC * NN];
__device__ unsigned short g_mth[CC * CC];            // Mt split [j][c]
__device__ unsigned short g_mtl[CC * CC];
__device__ float g_kv[CC * CC];
__device__ float g_ksum[CC];

// ---- smem: 3 stages of 4 compact planes (128 rows x 32 bf16 = 64B rows, XOR swizzle)
#define PAH  0
#define PAL  8192
#define PBH  16384
#define PBL  24576
#define SS   32768                  // bytes per stage
#define SMEM_DYN (3*SS + 3072)      // + bo/ks/z tail for out_mma

// ------------------------- helpers -------------------------
__device__ __forceinline__ unsigned smem_u32(const void* p){
    unsigned a;
    asm("{ .reg .u64 t; cvta.to.shared.u64 t, %1; cvt.u32.u64 %0, t; }":"=r"(a):"l"(p));
    return a;
}
__device__ __forceinline__ unsigned fsplit(float f){
    __nv_bfloat16 h = __float2bfloat16(f);
    __nv_bfloat16 l = __float2bfloat16(f - __bfloat162float(h));
    return (unsigned)__bfloat16_as_ushort(h) | ((unsigned)__bfloat16_as_ushort(l) << 16);
}
__device__ __forceinline__ float pkval(unsigned p){
    return __bfloat162float(__ushort_as_bfloat16((unsigned short)(p & 0xffffu)))
         + __bfloat162float(__ushort_as_bfloat16((unsigned short)(p >> 16)));
}
__device__ __forceinline__ void cpa16(unsigned d, const void* s){
    asm volatile("cp.async.cg.shared.global [%0], [%1], 16;" :: "r"(d), "l"(s));
}
__device__ __forceinline__ void cpcommit(){ asm volatile("cp.async.commit_group;" ::: "memory"); }
template<int N>
__device__ __forceinline__ void cpwaitg(){ asm volatile("cp.async.wait_group %0;" :: "n"(N) : "memory"); }

// swizzled byte offset of 16B chunk (row, chunk) inside a 128x64B plane
// s(row) = (row&3) ^ ((row>>2)&1); invariant under row += 16.
__device__ __forceinline__ unsigned swoff(int row, int chunk, int s){
    return (unsigned)(row*64 + ((chunk ^ s) << 4));
}
__device__ __forceinline__ void ldsm4(unsigned* r, unsigned addr){
    asm volatile("ldmatrix.sync.aligned.m8n8.x4.shared.b16 {%0,%1,%2,%3}, [%4];"
        : "=r"(r[0]),"=r"(r[1]),"=r"(r[2]),"=r"(r[3]) : "r"(addr));
}
__device__ __forceinline__ void mma16816(float* c, const unsigned* a, const unsigned* b){
    asm volatile("mma.sync.aligned.m16n8k16.row.col.f32.bf16.bf16.f32 "
        "{%0,%1,%2,%3},{%4,%5,%6,%7},{%8,%9},{%0,%1,%2,%3};"
        : "+f"(c[0]),"+f"(c[1]),"+f"(c[2]),"+f"(c[3])
        : "r"(a[0]),"r"(a[1]),"r"(a[2]),"r"(a[3]), "r"(b[0]),"r"(b[1]));
}
// one K=32 chunk: 2 k16 steps x 3 split terms over warp tile 32x64
__device__ __forceinline__ void chunk_mma(unsigned sbase, int wm, int wn, int lane, int sw,
                                          float acc[2][8][4]){
    const int arow = wm*32 + (lane & 15);
    const int akb  = (lane >> 4) & 1;
    const int brow = wn*64 + (lane & 7) + ((lane & 16) >> 1);
    const int bkb  = (lane >> 3) & 1;
#pragma unroll
    for (int s = 0; s < 2; ++s){
        const unsigned ca = (unsigned)((((s << 1) | akb) ^ sw) << 4);
        const unsigned cb = (unsigned)((((s << 1) | bkb) ^ sw) << 4);
        unsigned ah[2][4], al[2][4], bh[8][2], bl[8][2];
#pragma unroll
        for (int t = 0; t < 2; ++t){
            unsigned base = sbase + (unsigned)((arow + 16*t)*64) + ca;
            ldsm4(ah[t], base + PAH);
            ldsm4(al[t], base + PAL);
        }
#pragma unroll
        for (int u = 0; u < 4; ++u){
            unsigned base = sbase + (unsigned)((brow + 16*u)*64) + cb;
            unsigned r[4];
            ldsm4(r, base + PBH);
            bh[2*u][0]=r[0]; bh[2*u][1]=r[1]; bh[2*u+1][0]=r[2]; bh[2*u+1][1]=r[3];
            ldsm4(r, base + PBL);
            bl[2*u][0]=r[0]; bl[2*u][1]=r[1]; bl[2*u+1][0]=r[2]; bl[2*u+1][1]=r[3];
        }
#pragma unroll
        for (int t = 0; t < 2; ++t)
#pragma unroll
            for (int u = 0; u < 8; ++u){
                mma16816(acc[t][u], ah[t], bh[u]);
                mma16816(acc[t][u], ah[t], bl[u]);
                mma16816(acc[t][u], al[t], bh[u]);
            }
    }
}
__device__ __forceinline__ float elu1(float f){ return (f > 0.f) ? f + 1.f : expf(f); }

// ------------------------- presplit x and W -------------------------
__global__ void __launch_bounds__(256) presplit_x(const float* __restrict__ x)
{
    size_t i = ((size_t)blockIdx.x * 256 + threadIdx.x) * 4;
    float4 v = *(const float4*)(x + i);
    unsigned p0 = fsplit(v.x), p1 = fsplit(v.y), p2 = fsplit(v.z), p3 = fsplit(v.w);
    uint2 h, l;
    h.x = (p0&0xffffu)|(p1<<16); h.y = (p2&0xffffu)|(p3<<16);
    l.x = (p0>>16)|(p1&0xffff0000u); l.y = (p2>>16)|(p3&0xffff0000u);
    *(uint2*)(g_xh + i) = h;
    *(uint2*)(g_xl + i) = l;
}
__global__ void __launch_bounds__(256)
presplit_w(const float* __restrict__ Wq, const float* __restrict__ Wk,
           const float* __restrict__ Wv)
{
    int idx = blockIdx.x * 256 + threadIdx.x;
    int w = idx >> 14;
    size_t off = (size_t)w * 65536 + (size_t)(idx & 16383) * 4;
    const float* W = (w == 0) ? Wq : (w == 1) ? Wk : Wv;
    float4 v = *(const float4*)(W + (size_t)(idx & 16383) * 4);
    unsigned p0 = fsplit(v.x), p1 = fsplit(v.y), p2 = fsplit(v.z), p3 = fsplit(v.w);
    uint2 h, l;
    h.x = (p0&0xffffu)|(p1<<16); h.y = (p2&0xffffu)|(p3<<16);
    l.x = (p0>>16)|(p1&0xffff0000u); l.y = (p2>>16)|(p3&0xffff0000u);
    *(uint2*)(g_wh + off) = h;
    *(uint2*)(g_wl + off) = l;
}

__global__ void zero_kernel()
{
    int i = blockIdx.x * blockDim.x + threadIdx.x;
    if (i < CC*CC) g_kv[i] = 0.f;
    if (i < CC) g_ksum[i] = 0.f;
}

// ------------------------- qkv projections (3-stage, 1 barrier/chunk) ---------------------
__global__ void __launch_bounds__(256, 2)
qkv_mma()
{
    extern __shared__ __align__(128) unsigned char sm[];
    const unsigned sb = smem_u32(sm);
    unsigned* sm32 = (unsigned*)sm;                  // transpose buffer (stride 65 words)
    const int tid = threadIdx.x, lane = tid & 31, wid = tid >> 5;
    const int wm = wid >> 1, wn = wid & 1;
    const int r0 = blockIdx.x << 7;
    const int row = tid >> 1, e0 = (tid & 1) << 4;   // staged elems [e0, e0+16)
    const int c0 = (tid & 1) << 1;                   // first 16B chunk
    const int sws = ((row & 3) ^ ((row >> 2) & 1));  // store-side swizzle
    const int sw  = ((lane & 3) ^ ((lane >> 2) & 1)); // load-side swizzle
    const unsigned o1 = swoff(row, c0, sws), o2 = swoff(row, c0 + 1, sws);

    for (int w = 0; w < 3; ++w){
        for (int nh = 0; nh < 2; ++nh){
            float acc[2][8][4];
#pragma unroll
            for (int t = 0; t < 2; ++t)
#pragma unroll
                for (int u = 0; u < 8; ++u)
#pragma unroll
                    for (int e = 0; e < 4; ++e) acc[t][u][e] = 0.f;

            auto issue = [&](int c, int buf){
                const size_t oa = (size_t)(r0 + row)*CC + c*32 + e0;
                const size_t ob = (size_t)w*65536 + (size_t)(nh*128 + row)*CC + c*32 + e0;
                const unsigned d = sb + (unsigned)(buf*SS);
                cpa16(d + PAH + o1, g_xh + oa); cpa16(d + PAH + o2, g_xh + oa + 8);
                cpa16(d + PAL + o1, g_xl + oa); cpa16(d + PAL + o2, g_xl + oa + 8);
                cpa16(d + PBH + o1, g_wh + ob); cpa16(d + PBH + o2, g_wh + ob + 8);
                cpa16(d + PBL + o1, g_wl + ob); cpa16(d + PBL + o2, g_wl + ob + 8);
                cpcommit();
            };
            issue(0, 0);
            for (int c = 0; c < 8; ++c){
                if (c < 7){ issue(c + 1, (c + 1) % 3); cpwaitg<1>(); }
                else cpwaitg<0>();
                __syncthreads();
                chunk_mma(sb + (unsigned)((c % 3)*SS), wm, wn, lane, sw, acc);
            }

            if (w == 0){
#pragma unroll
                for (int t = 0; t < 2; ++t){
                    const int m = wm*32 + 16*t + (lane >> 2);
#pragma unroll
                    for (int u = 0; u < 8; ++u){
                        const int ng = nh*128 + wn*64 + u*8 + 2*(lane & 3);
                        uint2 o;
                        o.x = fsplit(elu1(acc[t][u][0]));
                        o.y = fsplit(elu1(acc[t][u][1]));
                        *(uint2*)(g_qpk + (size_t)(r0 + m)*CC + ng) = o;
                        o.x = fsplit(elu1(acc[t][u][2]));
                        o.y = fsplit(elu1(acc[t][u][3]));
                        *(uint2*)(g_qpk + (size_t)(r0 + m + 8)*CC + ng) = o;
                    }
                }
                __syncthreads();   // all reads of stage bufs done before next pass's issue(0,0)
            } else {
                unsigned short* Gh = (w == 1) ? g_kth : g_vth;
                unsigned short* Gl = (w == 1) ? g_ktl : g_vtl;
                for (int h4 = 0; h4 < 2; ++h4){
                    __syncthreads();
                    if (wn == h4){
#pragma unroll
                        for (int t = 0; t < 2; ++t){
                            const int m = wm*32 + 16*t + (lane >> 2);
#pragma unroll
                            for (int u = 0; u < 8; ++u){
                                const int nl = u*8 + 2*(lane & 3);
                                float f0 = acc[t][u][0], f1 = acc[t][u][1];
                                float f2 = acc[t][u][2], f3 = acc[t][u][3];
                                if (w == 1){ f0=elu1(f0); f1=elu1(f1); f2=elu1(f2); f3=elu1(f3); }
                                sm32[(m    )*65 + nl    ] = fsplit(f0);
                                sm32[(m    )*65 + nl + 1] = fsplit(f1);
                                sm32[(m + 8)*65 + nl    ] = fsplit(f2);
                                sm32[(m + 8)*65 + nl + 1] = fsplit(f3);
                            }
                        }
                    }
                    __syncthreads();
#pragma unroll
                    for (int j = 0; j < 8; ++j){
                        const int np = wid + 8*j;
                        const int ng = nh*128 + h4*64 + np;
                        float ks = 0.f;
#pragma unroll
                        for (int i = 0; i < 4; ++i){
                            unsigned p = sm32[(i*32 + lane)*65 + np];
                            Gh[(size_t)ng*NN + r0 + i*32 + lane] = (unsigned short)(p & 0xffffu);
                            Gl[(size_t)ng*NN + r0 + i*32 + lane] = (unsigned short)(p >> 16);
                            if (w == 1) ks += pkval(p);
                        }
                        if (w == 1){
#pragma unroll
                            for (int o = 16; o; o >>= 1) ks += __shfl_xor_sync(0xFFFFFFFFu, ks, o);
                            if (!lane) atomicAdd(&g_ksum[ng], ks);
                        }
                    }
                }
                __syncthreads();   // sm32 readers done before next pass prefetches buf0
            }
        }
    }
}

// ------------------------- kv = k^T v, split-K (3-stage, 1 barrier/chunk) -----------------
__global__ void __launch_bounds__(256, 2) kv_mma()
{
    extern __shared__ __align__(128) unsigned char sm[];
    const unsigned sb = smem_u32(sm);
    const int tid = threadIdx.x, lane = tid & 31, wid = tid >> 5;
    const int wm = wid >> 1, wn = wid & 1;
    const int a0 = blockIdx.x << 7, b0 = blockIdx.y << 7;
    const size_t i0 = (size_t)blockIdx.z * 4096;
    const int row = tid >> 1, e0 = (tid & 1) << 4;
    const int c0 = (tid & 1) << 1;
    const int sws = ((row & 3) ^ ((row >> 2) & 1));
    const int sw  = ((lane & 3) ^ ((lane >> 2) & 1));
    const unsigned o1 = swoff(row, c0, sws), o2 = swoff(row, c0 + 1, sws);

    float acc[2][8][4];
#pragma unroll
    for (int t = 0; t < 2; ++t)
#pragma unroll
        for (int u = 0; u < 8; ++u)
#pragma unroll
            for (int e = 0; e < 4; ++e) acc[t][u][e] = 0.f;

    auto issue = [&](int c, int buf){
        const size_t oa = (size_t)(a0 + row)*NN + i0 + c*32 + e0;
        const size_t ob = (size_t)(b0 + row)*NN + i0 + c*32 + e0;
        const unsigned d = sb + (unsigned)(buf*SS);
        cpa16(d + PAH + o1, g_kth + oa); cpa16(d + PAH + o2, g_kth + oa + 8);
        cpa16(d + PAL + o1, g_ktl + oa); cpa16(d + PAL + o2, g_ktl + oa + 8);
        cpa16(d + PBH + o1, g_vth + ob); cpa16(d + PBH + o2, g_vth + ob + 8);
        cpa16(d + PBL + o1, g_vtl + ob); cpa16(d + PBL + o2, g_vtl + ob + 8);
        cpcommit();
    };
    issue(0, 0);
    for (int c = 0; c < 128; ++c){
        if (c < 127){ issue(c + 1, (c + 1) % 3); cpwaitg<1>(); }
        else cpwaitg<0>();
        __syncthreads();
        chunk_mma(sb + (unsigned)((c % 3)*SS), wm, wn, lane, sw, acc);
    }
#pragma unroll
    for (int t = 0; t < 2; ++t){
        const int m = wm*32 + 16*t + (lane >> 2);
#pragma unroll
        for (int u = 0; u < 8; ++u){
            const int n = wn*64 + u*8 + 2*(lane & 3);
            atomicAdd(&g_kv[(a0 + m    )*CC + b0 + n    ], acc[t][u][0]);
            atomicAdd(&g_kv[(a0 + m    )*CC + b0 + n + 1], acc[t][u][1]);
            atomicAdd(&g_kv[(a0 + m + 8)*CC + b0 + n    ], acc[t][u][2]);
            atomicAdd(&g_kv[(a0 + m + 8)*CC + b0 + n + 1], acc[t][u][3]);
        }
    }
}

// ------------------------- Mt[j][a] = sum_b kv[a][b] Wo[j][b], split store ---------------
__global__ void __launch_bounds__(256) m_kernel(const float* __restrict__ Wo)
{
    __shared__ float wo_s[256];
    const int j = blockIdx.x, a = threadIdx.x;
    wo_s[a] = Wo[(size_t)j*CC + a];
    __syncthreads();
    const float* kvr = g_kv + (size_t)a*CC;
    float s = 0.f;
#pragma unroll 8
    for (int b = 0; b < CC; ++b) s += kvr[b] * wo_s[b];
    unsigned p = fsplit(s);
    g_mth[j*CC + a] = (unsigned short)(p & 0xffffu);
    g_mtl[j*CC + a] = (unsigned short)(p >> 16);
}

// ------------------------- out = z * (q @ Mt^T) + bo  (z fused) --------------------------
__global__ void __launch_bounds__(256, 2)
out_mma(const float* __restrict__ bo, float* __restrict__ out)
{
    extern __shared__ __align__(128) unsigned char sm[];
    const unsigned sb = smem_u32(sm);
    float* bo_s = (float*)(sm + 3*SS);
    float* ks_s = bo_s + 256;
    float* z_s  = ks_s + 256;
    const int tid = threadIdx.x, lane = tid & 31, wid = tid >> 5;
    const int wm = wid >> 1, wn = wid & 1;
    const int r0 = blockIdx.x << 7;
    const int row = tid >> 1, e0 = (tid & 1) << 4;
    const int c0 = (tid & 1) << 1;
    const int sws = ((row & 3) ^ ((row >> 2) & 1));
    const int sw  = ((lane & 3) ^ ((lane >> 2) & 1));
    const unsigned o1 = swoff(row, c0, sws), o2 = swoff(row, c0 + 1, sws);
    bo_s[tid] = bo[tid];
    ks_s[tid] = g_ksum[tid];
    __syncthreads();

    float zacc = 0.f;
    for (int nh = 0; nh < 2; ++nh){
        float acc[2][8][4];
#pragma unroll
        for (int t = 0; t < 2; ++t)
#pragma unroll
            for (int u = 0; u < 8; ++u)
#pragma unroll
                for (int e = 0; e < 4; ++e) acc[t][u][e] = 0.f;

        auto issueB = [&](int c, int buf){
            const size_t ob = (size_t)(nh*128 + row)*CC + c*32 + e0;
            const unsigned d = sb + (unsigned)(buf*SS);
            cpa16(d + PBH + o1, g_mth + ob); cpa16(d + PBH + o2, g_mth + ob + 8);
            cpa16(d + PBL + o1, g_mtl + ob); cpa16(d + PBL + o2, g_mtl + ob + 8);
            cpcommit();
        };
        issueB(0, 0);
        for (int c = 0; c < 8; ++c){
            // A register staging into buf c%3 (+ fused z on nh==0); safe: that buffer's
            // last readers (chunk c-3) finished before barrier B(c-1).
            {
                unsigned char* smb = sm + (c % 3)*SS;
                const unsigned* qs = g_qpk + (size_t)(r0 + row)*CC + c*32 + e0;
#pragma unroll
                for (int g = 0; g < 2; ++g){
                    uint4 A = *(const uint4*)(qs + g*8);
                    uint4 B = *(const uint4*)(qs + g*8 + 4);
                    unsigned p[8] = {A.x,A.y,A.z,A.w,B.x,B.y,B.z,B.w};
                    uint4 h, l;
                    h.x=(p[0]&0xffffu)|(p[1]<<16); h.y=(p[2]&0xffffu)|(p[3]<<16);
                    h.z=(p[4]&0xffffu)|(p[5]<<16); h.w=(p[6]&0xffffu)|(p[7]<<16);
                    l.x=(p[0]>>16)|(p[1]&0xffff0000u); l.y=(p[2]>>16)|(p[3]&0xffff0000u);
                    l.z=(p[4]>>16)|(p[5]&0xffff0000u); l.w=(p[6]>>16)|(p[7]&0xffff0000u);
                    const unsigned og = swoff(row, c0 + g, sws);
                    *(uint4*)(smb + PAH + og) = h;
                    *(uint4*)(smb + PAL + og) = l;
                    if (nh == 0){
                        const float* kp = ks_s + c*32 + e0 + g*8;
#pragma unroll
                        for (int u2 = 0; u2 < 8; ++u2) zacc += pkval(p[u2]) * kp[u2];
                    }
                }
            }
            if (c < 7){ issueB(c + 1, (c + 1) % 3); cpwaitg<1>(); }
            else cpwaitg<0>();
            __syncthreads();
            chunk_mma(sb + (unsigned)((c % 3)*SS), wm, wn, lane, sw, acc);
        }
        if (nh == 0){
            float s = zacc + __shfl_xor_sync(0xFFFFFFFFu, zacc, 1);
            if (!(tid & 1)) z_s[row] = 1.f / fmaxf(s, 1e-6f);
        }
        __syncthreads();   // z_s visible; stage-buf reads done before next pass's writes

#pragma unroll
        for (int t = 0; t < 2; ++t){
            const int m = wm*32 + 16*t + (lane >> 2);
            const float z0 = z_s[m], z1 = z_s[m + 8];
#pragma unroll
            for (int u = 0; u < 8; ++u){
                const int ng = nh*128 + wn*64 + u*8 + 2*(lane & 3);
                float2 o;
                o.x = acc[t][u][0]*z0 + bo_s[ng];
                o.y = acc[t][u][1]*z0 + bo_s[ng + 1];
                *(float2*)(out + (size_t)(r0 + m)*CC + ng) = o;
                o.x = acc[t][u][2]*z1 + bo_s[ng];
                o.y = acc[t][u][3]*z1 + bo_s[ng + 1];
                *(float2*)(out + (size_t)(r0 + m + 8)*CC + ng) = o;
            }
        }
    }
}

// ------------------------- launch -------------------------
extern "C" void kernel_launch(void* const* d_in, const int* in_sizes, int n_in,
                              void* d_out, int out_size)
{
    (void)in_sizes; (void)n_in; (void)out_size;
    const float* x  = (const float*)d_in[0];
    const float* Wq = (const float*)d_in[1];
    const float* Wk = (const float*)d_in[2];
    const float* Wv = (const float*)d_in[3];
    const float* Wo = (const float*)d_in[4];
    const float* bo = (const float*)d_in[5];
    float* out = (float*)d_out;

    static int inited = 0;
    if (!inited){
        cudaFuncSetAttribute(qkv_mma, cudaFuncAttributeMaxDynamicSharedMemorySize, SMEM_DYN);
        cudaFuncSetAttribute(kv_mma,  cudaFuncAttributeMaxDynamicSharedMemorySize, SMEM_DYN);
        cudaFuncSetAttribute(out_mma, cudaFuncAttributeMaxDynamicSharedMemorySize, SMEM_DYN);
        inited = 1;
    }

    zero_kernel<<<256, 256>>>();
    presplit_x<<<65536, 256>>>(x);
    presplit_w<<<192, 256>>>(Wq, Wk, Wv);
    qkv_mma<<<NN/128, 256, SMEM_DYN>>>();
    kv_mma<<<dim3(2, 2, 64), 256, SMEM_DYN>>>();
    m_kernel<<<256, 256>>>(Wo);
    out_mma<<<NN/128, 256, SMEM_DYN>>>(bo, out);
}